// round 5
// baseline (speedup 1.0000x reference)
#include <cuda_runtime.h>
#include <cuda.h>
#include <cstdint>
#include <cstddef>

// ---------------- problem dims ----------------
#define MB_   4096
#define DIN_  4096
#define HID_  16384
#define ONN_  1000
#define K2_   (DIN_ + HID_)

#define KC 128                  // int8 K per stage (128 B rows = SW128 atom)
#define NSTAGE 3
#define STAGE0_OFF 1024

// ---------------- static scratch (no allocation) ----------------
__device__ __align__(1024) int8_t g_xh [(size_t)MB_ * DIN_];
__device__ __align__(1024) int8_t g_xl [(size_t)MB_ * DIN_];
__device__ __align__(1024) int8_t g_w1h[(size_t)HID_ * DIN_];
__device__ __align__(1024) int8_t g_w1l[(size_t)HID_ * DIN_];
__device__ __align__(1024) int8_t g_w2h[(size_t)ONN_ * K2_];
__device__ __align__(1024) int8_t g_w2l[(size_t)ONN_ * K2_];
__device__ __align__(1024) int8_t g_a2h[(size_t)MB_ * K2_];
__device__ __align__(1024) int8_t g_a2l[(size_t)MB_ * K2_];
__device__ __align__(1024) float  g_h1f[(size_t)MB_ * HID_];
__device__ float g_sx[MB_];
__device__ float g_sw1[HID_];
__device__ float g_sw2[ONN_];
__device__ float g_s2[MB_];

// ---------------- PTX helpers ------------------
__device__ __forceinline__ uint32_t smem_u32(const void* p) {
    uint32_t a;
    asm("{ .reg .u64 t; cvta.to.shared.u64 t, %1; cvt.u32.u64 %0, t; }"
        : "=r"(a) : "l"(p));
    return a;
}

#define MBARRIER_INIT(addr, cnt) \
    asm volatile("mbarrier.init.shared.b64 [%0], %1;" :: "r"(addr), "r"(cnt) : "memory")

#define MBARRIER_EXPECT_TX(addr, bytes) \
    asm volatile("mbarrier.arrive.expect_tx.shared.b64 _, [%0], %1;" \
                 :: "r"(addr), "r"(bytes) : "memory")

#define MBARRIER_ARRIVE(addr) \
    asm volatile("mbarrier.arrive.shared.b64 _, [%0];" :: "r"(addr) : "memory")

#define MBARRIER_WAIT_PARITY(addr, parity) do {                                   \
    uint32_t _m = (addr); uint32_t _p = (parity); uint32_t _d;                    \
    asm volatile("{ .reg .pred p; mbarrier.try_wait.parity.acquire.cta.shared::cta.b64 p, [%1], %2; selp.b32 %0, 1, 0, p; }" \
        : "=r"(_d) : "r"(_m), "r"(_p) : "memory");                                \
    if (!_d) {                                                                    \
        asm volatile("{ .reg .pred P1; WL_%=: mbarrier.try_wait.parity.acquire.cta.shared::cta.b64 P1, [%0], %1, 0x989680; @P1 bra.uni WD_%=; bra.uni WL_%=; WD_%=: }" \
            :: "r"(_m), "r"(_p) : "memory");                                      \
    }                                                                             \
} while (0)

__device__ __forceinline__ void tma2d(uint32_t dst, const CUtensorMap* m,
                                      int cx, int cy, uint32_t mbar) {
    asm volatile(
        "cp.async.bulk.tensor.2d.shared::cta.global.tile.mbarrier::complete_tx::bytes "
        "[%0], [%1, {%2, %3}], [%4];"
        :: "r"(dst), "l"(m), "r"(cx), "r"(cy), "r"(mbar) : "memory");
}

#define FENCE_PROXY_ASYNC() asm volatile("fence.proxy.async.shared::cta;" ::: "memory")

__device__ __forceinline__ void ldsm4(uint32_t* r, uint32_t addr) {
    asm volatile("ldmatrix.sync.aligned.m8n8.x4.shared.b16 {%0,%1,%2,%3}, [%4];"
                 : "=r"(r[0]), "=r"(r[1]), "=r"(r[2]), "=r"(r[3]) : "r"(addr));
}

__device__ __forceinline__ void imma16832(int* c, const uint32_t* a, uint32_t b0, uint32_t b1) {
    asm volatile(
        "mma.sync.aligned.m16n8k32.row.col.s32.s8.s8.s32 "
        "{%0,%1,%2,%3}, {%4,%5,%6,%7}, {%8,%9}, {%0,%1,%2,%3};"
        : "+r"(c[0]), "+r"(c[1]), "+r"(c[2]), "+r"(c[3])
        : "r"(a[0]), "r"(a[1]), "r"(a[2]), "r"(a[3]), "r"(b0), "r"(b1));
}

// ---------------- row quantization --------------
// v ≈ s * (q_hi + q_lo/256), s = rowmax/127
__global__ __launch_bounds__(256)
void quant_rows(const float* __restrict__ src, int cols,
                int8_t* __restrict__ hi, int8_t* __restrict__ lo,
                float* __restrict__ scale)
{
    const int row = blockIdx.x;
    const float* p = src + (size_t)row * cols;
    __shared__ float red[256];
    const int tid = threadIdx.x;

    float mx = 0.f;
    for (int c = tid * 4; c < cols; c += 1024) {
        float4 v = *reinterpret_cast<const float4*>(p + c);
        mx = fmaxf(mx, fmaxf(fmaxf(fabsf(v.x), fabsf(v.y)),
                             fmaxf(fabsf(v.z), fabsf(v.w))));
    }
    red[tid] = mx;
    __syncthreads();
    for (int st = 128; st > 0; st >>= 1) {
        if (tid < st) red[tid] = fmaxf(red[tid], red[tid + st]);
        __syncthreads();
    }
    float m = red[0];
    float s = (m > 0.f) ? (m / 127.0f) : 1.0f;
    float inv = 1.0f / s;
    if (tid == 0) scale[row] = s;

    for (int c = tid * 4; c < cols; c += 1024) {
        float4 v = *reinterpret_cast<const float4*>(p + c);
        char4 qh, ql;
        float q, r, l;
        q = rintf(v.x * inv); r = v.x - q * s; l = fminf(fmaxf(rintf(r * inv * 256.f), -127.f), 127.f);
        qh.x = (int8_t)(int)q; ql.x = (int8_t)(int)l;
        q = rintf(v.y * inv); r = v.y - q * s; l = fminf(fmaxf(rintf(r * inv * 256.f), -127.f), 127.f);
        qh.y = (int8_t)(int)q; ql.y = (int8_t)(int)l;
        q = rintf(v.z * inv); r = v.z - q * s; l = fminf(fmaxf(rintf(r * inv * 256.f), -127.f), 127.f);
        qh.z = (int8_t)(int)q; ql.z = (int8_t)(int)l;
        q = rintf(v.w * inv); r = v.w - q * s; l = fminf(fmaxf(rintf(r * inv * 256.f), -127.f), 127.f);
        qh.w = (int8_t)(int)q; ql.w = (int8_t)(int)l;
        *reinterpret_cast<char4*>(hi + (size_t)row * cols + c) = qh;
        *reinterpret_cast<char4*>(lo + (size_t)row * cols + c) = ql;
    }
}

// concat(x_row, h1_row) -> single-scale int8 row of A2
__global__ __launch_bounds__(256)
void quant_concat(const float* __restrict__ x)
{
    const int row = blockIdx.x;
    const float* px = x + (size_t)row * DIN_;
    const float* ph = g_h1f + (size_t)row * HID_;
    __shared__ float red[256];
    const int tid = threadIdx.x;

    float mx = 0.f;
    for (int c = tid * 4; c < DIN_; c += 1024) {
        float4 v = *reinterpret_cast<const float4*>(px + c);
        mx = fmaxf(mx, fmaxf(fmaxf(fabsf(v.x), fabsf(v.y)),
                             fmaxf(fabsf(v.z), fabsf(v.w))));
    }
    for (int c = tid * 4; c < HID_; c += 1024) {
        float4 v = *reinterpret_cast<const float4*>(ph + c);
        mx = fmaxf(mx, fmaxf(fmaxf(fabsf(v.x), fabsf(v.y)),
                             fmaxf(fabsf(v.z), fabsf(v.w))));
    }
    red[tid] = mx;
    __syncthreads();
    for (int st = 128; st > 0; st >>= 1) {
        if (tid < st) red[tid] = fmaxf(red[tid], red[tid + st]);
        __syncthreads();
    }
    float m = red[0];
    float s = (m > 0.f) ? (m / 127.0f) : 1.0f;
    float inv = 1.0f / s;
    if (tid == 0) g_s2[row] = s;

    int8_t* dh = g_a2h + (size_t)row * K2_;
    int8_t* dl = g_a2l + (size_t)row * K2_;
    #pragma unroll 1
    for (int seg = 0; seg < 2; seg++) {
        const float* p = seg ? ph : px;
        const int cols = seg ? HID_ : DIN_;
        const int off  = seg ? DIN_ : 0;
        for (int c = tid * 4; c < cols; c += 1024) {
            float4 v = *reinterpret_cast<const float4*>(p + c);
            char4 qh, ql;
            float q, r, l;
            q = rintf(v.x * inv); r = v.x - q * s; l = fminf(fmaxf(rintf(r * inv * 256.f), -127.f), 127.f);
            qh.x = (int8_t)(int)q; ql.x = (int8_t)(int)l;
            q = rintf(v.y * inv); r = v.y - q * s; l = fminf(fmaxf(rintf(r * inv * 256.f), -127.f), 127.f);
            qh.y = (int8_t)(int)q; ql.y = (int8_t)(int)l;
            q = rintf(v.z * inv); r = v.z - q * s; l = fminf(fmaxf(rintf(r * inv * 256.f), -127.f), 127.f);
            qh.z = (int8_t)(int)q; ql.z = (int8_t)(int)l;
            q = rintf(v.w * inv); r = v.w - q * s; l = fminf(fmaxf(rintf(r * inv * 256.f), -127.f), 127.f);
            qh.w = (int8_t)(int)q; ql.w = (int8_t)(int)l;
            *reinterpret_cast<char4*>(dh + off + c) = qh;
            *reinterpret_cast<char4*>(dl + off + c) = ql;
        }
    }
}

// ---------------- IMMA GEMM ---------------------
// out = sA[m]*sB[n]*(acc_hh + acc_mid/256) + bias ; 3 int8 passes per K-chunk.
// MODE 0: relu -> fp32 g_h1f.   MODE 1: fp32 outp, cols guarded to ONN_.
template <int MODE, int TBM>
__global__ __launch_bounds__(256, 1)
void gemm_imma(const __grid_constant__ CUtensorMap aH,
               const __grid_constant__ CUtensorMap aL,
               const __grid_constant__ CUtensorMap bH,
               const __grid_constant__ CUtensorMap bL,
               int T,
               const float* __restrict__ sa,
               const float* __restrict__ sb,
               const float* __restrict__ bias,
               float* __restrict__ outp)
{
    constexpr int MI = TBM / 32;
    constexpr uint32_t ASZ = (uint32_t)TBM * 128u;
    constexpr uint32_t STG_AH = 0;
    constexpr uint32_t STG_AL = ASZ;
    constexpr uint32_t STG_BH = 2u * ASZ;
    constexpr uint32_t STG_BL = 2u * ASZ + 16384u;
    constexpr uint32_t STAGE_SZ = 2u * ASZ + 32768u;

    extern __shared__ __align__(1024) char smem[];
    const uint32_t sbase = smem_u32(smem);

    const int tid  = threadIdx.x;
    const int lane = tid & 31;
    const int wid  = tid >> 5;
    const int wm   = (wid & 1) * (TBM / 2);
    const int wn   = (wid >> 1) * 32;

    if (tid == 0) {
        #pragma unroll
        for (int s = 0; s < NSTAGE; s++) {
            MBARRIER_INIT(sbase + 8u * s, 1);
            MBARRIER_INIT(sbase + 64u + 8u * s, 8);
        }
        FENCE_PROXY_ASYNC();
    }
    __syncthreads();

    const int m0 = blockIdx.x * TBM;
    const int n0 = blockIdx.y * 128;

    const uint32_t rowoff = (uint32_t)(lane & 15) * 128u;
    const uint32_t hi4 = (uint32_t)(lane >> 4);
    const uint32_t lo7 = (uint32_t)(lane & 7);
    uint32_t cb[4];
    #pragma unroll
    for (int ks = 0; ks < 4; ks++)
        cb[ks] = (((2u * ks + hi4) ^ lo7) << 4);

    int accA[MI][4][4], accB[MI][4][4];
    #pragma unroll
    for (int mi = 0; mi < MI; mi++)
        #pragma unroll
        for (int ni = 0; ni < 4; ni++)
            #pragma unroll
            for (int q = 0; q < 4; q++) { accA[mi][ni][q] = 0; accB[mi][ni][q] = 0; }

    if (tid == 0) {
        #pragma unroll
        for (int j = 0; j < NSTAGE; j++) {
            const uint32_t full = sbase + 8u * j;
            MBARRIER_EXPECT_TX(full, STAGE_SZ);
            const uint32_t sb_ = sbase + STAGE0_OFF + (uint32_t)j * STAGE_SZ;
            tma2d(sb_ + STG_AH, &aH, j * KC, m0, full);
            tma2d(sb_ + STG_AL, &aL, j * KC, m0, full);
            tma2d(sb_ + STG_BH, &bH, j * KC, n0, full);
            tma2d(sb_ + STG_BL, &bL, j * KC, n0, full);
        }
    }

    int s = 0, ph = 0;
    #pragma unroll 1
    for (int i = 0; i < T; i++) {
        MBARRIER_WAIT_PARITY(sbase + 8u * s, (uint32_t)ph);

        const uint32_t sb_ = sbase + STAGE0_OFF + (uint32_t)s * STAGE_SZ;
        const uint32_t aHb = sb_ + STG_AH + (uint32_t)wm * 128u + rowoff;
        const uint32_t aLb = sb_ + STG_AL + (uint32_t)wm * 128u + rowoff;
        const uint32_t bHb = sb_ + STG_BH + (uint32_t)wn * 128u + rowoff;
        const uint32_t bLb = sb_ + STG_BL + (uint32_t)wn * 128u + rowoff;

        #pragma unroll
        for (int ks = 0; ks < 4; ks++) {
            uint32_t ah[MI][4], al[MI][4], bb[2][4];
            #pragma unroll
            for (int mi = 0; mi < MI; mi++)
                ldsm4(ah[mi], aHb + (uint32_t)mi * (16u * 128u) + cb[ks]);
            #pragma unroll
            for (int mi = 0; mi < MI; mi++)
                ldsm4(al[mi], aLb + (uint32_t)mi * (16u * 128u) + cb[ks]);
            #pragma unroll
            for (int nj = 0; nj < 2; nj++)
                ldsm4(bb[nj], bHb + (uint32_t)nj * (16u * 128u) + cb[ks]);

            // hh -> accA ; lh -> accB (B_hi in regs)
            #pragma unroll
            for (int mi = 0; mi < MI; mi++)
                #pragma unroll
                for (int ni = 0; ni < 4; ni++) {
                    const uint32_t b0 = bb[ni >> 1][ni & 1];
                    const uint32_t b1 = bb[ni >> 1][(ni & 1) + 2];
                    imma16832(accA[mi][ni], ah[mi], b0, b1);
                }
            #pragma unroll
            for (int mi = 0; mi < MI; mi++)
                #pragma unroll
                for (int ni = 0; ni < 4; ni++) {
                    const uint32_t b0 = bb[ni >> 1][ni & 1];
                    const uint32_t b1 = bb[ni >> 1][(ni & 1) + 2];
                    imma16832(accB[mi][ni], al[mi], b0, b1);
                }
            // hl -> accB
            #pragma unroll
            for (int nj = 0; nj < 2; nj++)
                ldsm4(bb[nj], bLb + (uint32_t)nj * (16u * 128u) + cb[ks]);
            #pragma unroll
            for (int mi = 0; mi < MI; mi++)
                #pragma unroll
                for (int ni = 0; ni < 4; ni++) {
                    const uint32_t b0 = bb[ni >> 1][ni & 1];
                    const uint32_t b1 = bb[ni >> 1][(ni & 1) + 2];
                    imma16832(accB[mi][ni], ah[mi], b0, b1);
                }
        }

        if (lane == 0) MBARRIER_ARRIVE(sbase + 64u + 8u * s);

        const int j = i + NSTAGE;
        if (tid == 0 && j < T) {
            MBARRIER_WAIT_PARITY(sbase + 64u + 8u * s, (uint32_t)ph);
            const uint32_t full = sbase + 8u * s;
            MBARRIER_EXPECT_TX(full, STAGE_SZ);
            tma2d(sb_ + STG_AH, &aH, j * KC, m0, full);
            tma2d(sb_ + STG_AL, &aL, j * KC, m0, full);
            tma2d(sb_ + STG_BH, &bH, j * KC, n0, full);
            tma2d(sb_ + STG_BL, &bL, j * KC, n0, full);
        }
        if (++s == NSTAGE) { s = 0; ph ^= 1; }
    }

    // ---------------- epilogue ----------------
    const int mrow = m0 + wm + (lane >> 2);
    const int ncol = n0 + wn + 2 * (lane & 3);

    #pragma unroll
    for (int mi = 0; mi < MI; mi++) {
        const int ma = mrow + mi * 16;
        const int mb = ma + 8;
        const float sa_a = __ldg(sa + ma);
        const float sa_b = __ldg(sa + mb);
        #pragma unroll
        for (int ni = 0; ni < 4; ni++) {
            const int n = ncol + ni * 8;
            if (MODE == 1 && n >= ONN_) continue;
            const float2 sbv = __ldg(reinterpret_cast<const float2*>(sb + n));
            const float2 bv  = __ldg(reinterpret_cast<const float2*>(bias + n));
            const float k = 0.00390625f;   // 1/256
            float v00 = ((float)accA[mi][ni][0] + (float)accB[mi][ni][0] * k) * (sa_a * sbv.x) + bv.x;
            float v01 = ((float)accA[mi][ni][1] + (float)accB[mi][ni][1] * k) * (sa_a * sbv.y) + bv.y;
            float v10 = ((float)accA[mi][ni][2] + (float)accB[mi][ni][2] * k) * (sa_b * sbv.x) + bv.x;
            float v11 = ((float)accA[mi][ni][3] + (float)accB[mi][ni][3] * k) * (sa_b * sbv.y) + bv.y;
            if (MODE == 0) {
                v00 = v00 > 0.f ? v00 : 0.f;
                v01 = v01 > 0.f ? v01 : 0.f;
                v10 = v10 > 0.f ? v10 : 0.f;
                v11 = v11 > 0.f ? v11 : 0.f;
                float2 o0 = { v00, v01 };
                float2 o1 = { v10, v11 };
                *reinterpret_cast<float2*>(g_h1f + (size_t)ma * HID_ + n) = o0;
                *reinterpret_cast<float2*>(g_h1f + (size_t)mb * HID_ + n) = o1;
            } else {
                float2 o0 = { v00, v01 };
                float2 o1 = { v10, v11 };
                *reinterpret_cast<float2*>(outp + (size_t)ma * ONN_ + n) = o0;
                *reinterpret_cast<float2*>(outp + (size_t)mb * ONN_ + n) = o1;
            }
        }
    }
}

// ---------------- host side ---------------------
typedef CUresult (*PFN_tmap)(CUtensorMap*, CUtensorMapDataType, cuuint32_t, void*,
                             const cuuint64_t*, const cuuint64_t*, const cuuint32_t*,
                             const cuuint32_t*, CUtensorMapInterleave, CUtensorMapSwizzle,
                             CUtensorMapL2promotion, CUtensorMapFloatOOBfill);

static void mk2d_i8(PFN_tmap f, CUtensorMap* m, void* p,
                    unsigned long long k, unsigned long long rows, unsigned box1)
{
    cuuint64_t dims[2] = { k, rows };
    cuuint64_t str[1]  = { k };            // row stride in bytes (int8)
    cuuint32_t box[2]  = { 128u, box1 };
    cuuint32_t es[2]   = { 1u, 1u };
    f(m, CU_TENSOR_MAP_DATA_TYPE_UINT8, 2, p, dims, str, box, es,
      CU_TENSOR_MAP_INTERLEAVE_NONE, CU_TENSOR_MAP_SWIZZLE_128B,
      CU_TENSOR_MAP_L2_PROMOTION_L2_128B, CU_TENSOR_MAP_FLOAT_OOB_FILL_NONE);
}

extern "C" void kernel_launch(void* const* d_in, const int* in_sizes, int n_in,
                              void* d_out, int out_size)
{
    const float* x  = (const float*)d_in[0];
    const float* W1 = (const float*)d_in[1];
    const float* b1 = (const float*)d_in[2];
    const float* W2 = (const float*)d_in[3];
    const float* b2 = (const float*)d_in[4];
    float* out = (float*)d_out;

    void *xh, *xl, *w1h, *w1l, *w2h, *w2l, *a2h, *a2l;
    void *sx, *sw1, *sw2, *s2;
    cudaGetSymbolAddress(&xh,  g_xh);  cudaGetSymbolAddress(&xl,  g_xl);
    cudaGetSymbolAddress(&w1h, g_w1h); cudaGetSymbolAddress(&w1l, g_w1l);
    cudaGetSymbolAddress(&w2h, g_w2h); cudaGetSymbolAddress(&w2l, g_w2l);
    cudaGetSymbolAddress(&a2h, g_a2h); cudaGetSymbolAddress(&a2l, g_a2l);
    cudaGetSymbolAddress(&sx,  g_sx);  cudaGetSymbolAddress(&sw1, g_sw1);
    cudaGetSymbolAddress(&sw2, g_sw2); cudaGetSymbolAddress(&s2,  g_s2);

    // quantize inputs
    quant_rows<<<MB_,  256>>>(x,  DIN_, (int8_t*)xh,  (int8_t*)xl,  (float*)sx);
    quant_rows<<<HID_, 256>>>(W1, DIN_, (int8_t*)w1h, (int8_t*)w1l, (float*)sw1);
    quant_rows<<<ONN_, 256>>>(W2, K2_,  (int8_t*)w2h, (int8_t*)w2l, (float*)sw2);

    // tensor maps via driver entry point
    PFN_tmap enc = nullptr;
    cudaDriverEntryPointQueryResult qr;
    cudaGetDriverEntryPoint("cuTensorMapEncodeTiled", (void**)&enc,
                            cudaEnableDefault, &qr);

    CUtensorMap m_xh, m_xl, m_w1h, m_w1l, m_a2h, m_a2l, m_w2h, m_w2l;
    mk2d_i8(enc, &m_xh,  xh,  DIN_, MB_,  128);
    mk2d_i8(enc, &m_xl,  xl,  DIN_, MB_,  128);
    mk2d_i8(enc, &m_w1h, w1h, DIN_, HID_, 128);
    mk2d_i8(enc, &m_w1l, w1l, DIN_, HID_, 128);
    mk2d_i8(enc, &m_a2h, a2h, K2_,  MB_,  64);
    mk2d_i8(enc, &m_a2l, a2l, K2_,  MB_,  64);
    mk2d_i8(enc, &m_w2h, w2h, K2_,  ONN_, 128);   // OOB rows (>=1000) zero-filled
    mk2d_i8(enc, &m_w2l, w2l, K2_,  ONN_, 128);

    const int smem1 = STAGE0_OFF + NSTAGE * (2 * 128 * 128 + 32768);   // 197632
    const int smem2 = STAGE0_OFF + NSTAGE * (2 * 64  * 128 + 32768);   // 148480
    cudaFuncSetAttribute(gemm_imma<0,128>, cudaFuncAttributeMaxDynamicSharedMemorySize, smem1);
    cudaFuncSetAttribute(gemm_imma<1,64>,  cudaFuncAttributeMaxDynamicSharedMemorySize, smem2);

    // GEMM1: h1 = relu(x @ W1^T + b1) -> fp32 scratch
    dim3 g1(MB_ / 128, HID_ / 128);   // (32, 128)
    gemm_imma<0,128><<<g1, 256, smem1>>>(m_xh, m_xl, m_w1h, m_w1l,
                                         DIN_ / KC, (const float*)sx,
                                         (const float*)sw1, b1, nullptr);

    // build concat A2 (single row scale over [x | h1])
    quant_concat<<<MB_, 256>>>(x);

    // GEMM2: out = A2 @ W2^T + b2
    dim3 g2(MB_ / 64, 8);             // (64, 8)
    gemm_imma<1,64><<<g2, 256, smem2>>>(m_a2h, m_a2l, m_w2h, m_w2l,
                                        K2_ / KC, (const float*)s2,
                                        (const float*)sw2, b2, out);
}

// round 6
// speedup vs baseline: 2.7815x; 2.7815x over previous
#include <cuda_runtime.h>
#include <cuda_bf16.h>
#include <cuda.h>
#include <cstdint>
#include <cstddef>

// ---------------- problem dims ----------------
#define MB_   4096
#define DIN_  4096
#define HID_  16384
#define ONN_  1000
#define K2_   (DIN_ + HID_)

#define KC 64                   // bf16 K per stage (128 B rows = SW128 atom)
#define STAGE0_OFF 1024

// bf16 split scratch (static device arrays — no allocation)
__device__ __align__(1024) __nv_bfloat16 g_xh [(size_t)MB_ * DIN_];
__device__ __align__(1024) __nv_bfloat16 g_xl [(size_t)MB_ * DIN_];
__device__ __align__(1024) __nv_bfloat16 g_w1h[(size_t)HID_ * DIN_];
__device__ __align__(1024) __nv_bfloat16 g_w1l[(size_t)HID_ * DIN_];
__device__ __align__(1024) __nv_bfloat16 g_w2h[(size_t)ONN_ * K2_];
__device__ __align__(1024) __nv_bfloat16 g_w2l[(size_t)ONN_ * K2_];
__device__ __align__(1024) __nv_bfloat16 g_h1h[(size_t)MB_ * HID_];
__device__ __align__(1024) __nv_bfloat16 g_h1l[(size_t)MB_ * HID_];

// ---------------- PTX helpers ------------------
__device__ __forceinline__ uint32_t smem_u32(const void* p) {
    uint32_t a;
    asm("{ .reg .u64 t; cvta.to.shared.u64 t, %1; cvt.u32.u64 %0, t; }"
        : "=r"(a) : "l"(p));
    return a;
}

#define MBARRIER_INIT(addr, cnt) \
    asm volatile("mbarrier.init.shared.b64 [%0], %1;" :: "r"(addr), "r"(cnt) : "memory")

#define MBARRIER_EXPECT_TX(addr, bytes) \
    asm volatile("mbarrier.arrive.expect_tx.shared.b64 _, [%0], %1;" \
                 :: "r"(addr), "r"(bytes) : "memory")

#define MBARRIER_ARRIVE(addr) \
    asm volatile("mbarrier.arrive.shared.b64 _, [%0];" :: "r"(addr) : "memory")

#define MBARRIER_WAIT_PARITY(addr, parity) do {                                   \
    uint32_t _m = (addr); uint32_t _p = (parity); uint32_t _d;                    \
    asm volatile("{ .reg .pred p; mbarrier.try_wait.parity.acquire.cta.shared::cta.b64 p, [%1], %2; selp.b32 %0, 1, 0, p; }" \
        : "=r"(_d) : "r"(_m), "r"(_p) : "memory");                                \
    if (!_d) {                                                                    \
        asm volatile("{ .reg .pred P1; WL_%=: mbarrier.try_wait.parity.acquire.cta.shared::cta.b64 P1, [%0], %1, 0x989680; @P1 bra.uni WD_%=; bra.uni WL_%=; WD_%=: }" \
            :: "r"(_m), "r"(_p) : "memory");                                      \
    }                                                                             \
} while (0)

__device__ __forceinline__ void tma2d(uint32_t dst, const CUtensorMap* m,
                                      int cx, int cy, uint32_t mbar) {
    asm volatile(
        "cp.async.bulk.tensor.2d.shared::cta.global.tile.mbarrier::complete_tx::bytes "
        "[%0], [%1, {%2, %3}], [%4];"
        :: "r"(dst), "l"(m), "r"(cx), "r"(cy), "r"(mbar) : "memory");
}

#define FENCE_PROXY_ASYNC() asm volatile("fence.proxy.async.shared::cta;" ::: "memory")

__device__ __forceinline__ void ldsm4(uint32_t* r, uint32_t addr) {
    asm volatile("ldmatrix.sync.aligned.m8n8.x4.shared.b16 {%0,%1,%2,%3}, [%4];"
                 : "=r"(r[0]), "=r"(r[1]), "=r"(r[2]), "=r"(r[3]) : "r"(addr));
}

__device__ __forceinline__ void mma16816(float* c, const uint32_t* a, uint32_t b0, uint32_t b1) {
    asm volatile(
        "mma.sync.aligned.m16n8k16.row.col.f32.bf16.bf16.f32 "
        "{%0,%1,%2,%3}, {%4,%5,%6,%7}, {%8,%9}, {%0,%1,%2,%3};"
        : "+f"(c[0]), "+f"(c[1]), "+f"(c[2]), "+f"(c[3])
        : "r"(a[0]), "r"(a[1]), "r"(a[2]), "r"(a[3]), "r"(b0), "r"(b1));
}

// ---------------- split conversion --------------
__global__ void split_fp32(const float* __restrict__ src,
                           __nv_bfloat16* __restrict__ hi,
                           __nv_bfloat16* __restrict__ lo, size_t n4)
{
    size_t i = (size_t)blockIdx.x * blockDim.x + threadIdx.x;
    if (i >= n4) return;
    float4 v = reinterpret_cast<const float4*>(src)[i];
    __nv_bfloat16 h0 = __float2bfloat16_rn(v.x);
    __nv_bfloat16 h1 = __float2bfloat16_rn(v.y);
    __nv_bfloat16 h2 = __float2bfloat16_rn(v.z);
    __nv_bfloat16 h3 = __float2bfloat16_rn(v.w);
    __nv_bfloat16 l0 = __float2bfloat16_rn(v.x - __bfloat162float(h0));
    __nv_bfloat16 l1 = __float2bfloat16_rn(v.y - __bfloat162float(h1));
    __nv_bfloat16 l2 = __float2bfloat16_rn(v.z - __bfloat162float(h2));
    __nv_bfloat16 l3 = __float2bfloat16_rn(v.w - __bfloat162float(h3));
    uint2 ph, pl;
    ph.x = (uint32_t)__bfloat16_as_ushort(h0) | ((uint32_t)__bfloat16_as_ushort(h1) << 16);
    ph.y = (uint32_t)__bfloat16_as_ushort(h2) | ((uint32_t)__bfloat16_as_ushort(h3) << 16);
    pl.x = (uint32_t)__bfloat16_as_ushort(l0) | ((uint32_t)__bfloat16_as_ushort(l1) << 16);
    pl.y = (uint32_t)__bfloat16_as_ushort(l2) | ((uint32_t)__bfloat16_as_ushort(l3) << 16);
    reinterpret_cast<uint2*>(hi)[i] = ph;
    reinterpret_cast<uint2*>(lo)[i] = pl;
}

// ---------------- HMMA GEMM ---------------------
// 128 threads = 4 warps in 2(M) x 2(N); two CTAs co-resident per SM.
// D[TBM,BN] += (Ah+Al)@(Bh+Bl)^T  (3-term bf16 split), K streamed by TMA.
// MODE 0: relu(acc+bias) -> split bf16 g_h1h/g_h1l.  MODE 1: acc+bias -> fp32.
template <int MODE, int TBM, int BN, int NST>
__global__ __launch_bounds__(128, 2)
void gemm_hmma(const __grid_constant__ CUtensorMap a0h,
               const __grid_constant__ CUtensorMap a0l,
               const __grid_constant__ CUtensorMap a1h,
               const __grid_constant__ CUtensorMap a1l,
               const __grid_constant__ CUtensorMap bh,
               const __grid_constant__ CUtensorMap bl,
               int K0, int K1, int bk1,
               const float* __restrict__ bias,
               float* __restrict__ outp)
{
    constexpr int MI = TBM / 32;                      // 16-row A frags per warp
    constexpr uint32_t ASZ = (uint32_t)TBM * 128u;
    constexpr uint32_t BSZ = (uint32_t)BN * 128u;
    constexpr uint32_t STG_AH = 0;
    constexpr uint32_t STG_AL = ASZ;
    constexpr uint32_t STG_BH = 2u * ASZ;
    constexpr uint32_t STG_BL = 2u * ASZ + BSZ;
    constexpr uint32_t STAGE_SZ = 2u * ASZ + 2u * BSZ;

    extern __shared__ __align__(1024) char smem[];
    const uint32_t sbase = smem_u32(smem);

    const int tid  = threadIdx.x;
    const int lane = tid & 31;
    const int wid  = tid >> 5;
    const int wm   = (wid & 1) * (TBM / 2);
    const int wn   = (wid >> 1) * (BN / 2);

    if (tid == 0) {
        #pragma unroll
        for (int s = 0; s < NST; s++) {
            MBARRIER_INIT(sbase + 8u * s, 1);            // FULL[s]
            MBARRIER_INIT(sbase + 64u + 8u * s, 4);      // EMPTY[s] (per-warp)
        }
        FENCE_PROXY_ASYNC();
    }
    __syncthreads();

    const int m0 = blockIdx.x * TBM;
    const int n0 = blockIdx.y * BN;
    const int S0 = K0 / KC;
    const int T  = (K0 + K1) / KC;

    // per-lane ldmatrix addressing pieces (SW128 swizzle: chunk ^= row&7)
    const uint32_t rowoff = (uint32_t)(lane & 15) * 128u;
    const uint32_t hi4 = (uint32_t)(lane >> 4);
    const uint32_t lo7 = (uint32_t)(lane & 7);
    uint32_t cb[4];
    #pragma unroll
    for (int ks = 0; ks < 4; ks++)
        cb[ks] = (((2u * ks + hi4) ^ lo7) << 4);

    float acc[MI][4][4];
    #pragma unroll
    for (int mi = 0; mi < MI; mi++)
        #pragma unroll
        for (int ni = 0; ni < 4; ni++)
            #pragma unroll
            for (int q = 0; q < 4; q++) acc[mi][ni][q] = 0.f;

    if (tid == 0) {
        #pragma unroll
        for (int j = 0; j < NST; j++) {
            const uint32_t full = sbase + 8u * j;
            MBARRIER_EXPECT_TX(full, STAGE_SZ);
            const uint32_t sb = sbase + STAGE0_OFF + (uint32_t)j * STAGE_SZ;
            const CUtensorMap *mah, *mal; int ak, bk;
            if (j < S0) { mah = &a0h; mal = &a0l; ak = j * KC; bk = j * KC; }
            else        { mah = &a1h; mal = &a1l; ak = (j - S0) * KC; bk = bk1 + (j - S0) * KC; }
            tma2d(sb + STG_AH, mah, ak, m0, full);
            tma2d(sb + STG_AL, mal, ak, m0, full);
            tma2d(sb + STG_BH, &bh, bk, n0, full);
            tma2d(sb + STG_BL, &bl, bk, n0, full);
        }
    }

    int s = 0, ph = 0;
    #pragma unroll 1
    for (int i = 0; i < T; i++) {
        MBARRIER_WAIT_PARITY(sbase + 8u * s, (uint32_t)ph);

        const uint32_t sb  = sbase + STAGE0_OFF + (uint32_t)s * STAGE_SZ;
        const uint32_t aHb = sb + STG_AH + (uint32_t)wm * 128u + rowoff;
        const uint32_t aLb = sb + STG_AL + (uint32_t)wm * 128u + rowoff;
        const uint32_t bHb = sb + STG_BH + (uint32_t)wn * 128u + rowoff;
        const uint32_t bLb = sb + STG_BL + (uint32_t)wn * 128u + rowoff;

        #pragma unroll
        for (int ks = 0; ks < 4; ks++) {
            uint32_t ah[MI][4], al[MI][4], bb[2][4];
            #pragma unroll
            for (int mi = 0; mi < MI; mi++)
                ldsm4(ah[mi], aHb + (uint32_t)mi * (16u * 128u) + cb[ks]);
            #pragma unroll
            for (int mi = 0; mi < MI; mi++)
                ldsm4(al[mi], aLb + (uint32_t)mi * (16u * 128u) + cb[ks]);
            #pragma unroll
            for (int nj = 0; nj < 2; nj++)
                ldsm4(bb[nj], bHb + (uint32_t)nj * (16u * 128u) + cb[ks]);

            #pragma unroll
            for (int mi = 0; mi < MI; mi++)
                #pragma unroll
                for (int ni = 0; ni < 4; ni++) {
                    const uint32_t b0 = bb[ni >> 1][ni & 1];
                    const uint32_t b1 = bb[ni >> 1][(ni & 1) + 2];
                    mma16816(acc[mi][ni], ah[mi], b0, b1);
                }
            #pragma unroll
            for (int mi = 0; mi < MI; mi++)
                #pragma unroll
                for (int ni = 0; ni < 4; ni++) {
                    const uint32_t b0 = bb[ni >> 1][ni & 1];
                    const uint32_t b1 = bb[ni >> 1][(ni & 1) + 2];
                    mma16816(acc[mi][ni], al[mi], b0, b1);
                }
            #pragma unroll
            for (int nj = 0; nj < 2; nj++)
                ldsm4(bb[nj], bLb + (uint32_t)nj * (16u * 128u) + cb[ks]);
            #pragma unroll
            for (int mi = 0; mi < MI; mi++)
                #pragma unroll
                for (int ni = 0; ni < 4; ni++) {
                    const uint32_t b0 = bb[ni >> 1][ni & 1];
                    const uint32_t b1 = bb[ni >> 1][(ni & 1) + 2];
                    mma16816(acc[mi][ni], ah[mi], b0, b1);
                }
        }

        if (lane == 0) MBARRIER_ARRIVE(sbase + 64u + 8u * s);

        const int j = i + NST;
        if (tid == 0 && j < T) {
            MBARRIER_WAIT_PARITY(sbase + 64u + 8u * s, (uint32_t)ph);
            const uint32_t full = sbase + 8u * s;
            MBARRIER_EXPECT_TX(full, STAGE_SZ);
            const CUtensorMap *mah, *mal; int ak, bk;
            if (j < S0) { mah = &a0h; mal = &a0l; ak = j * KC; bk = j * KC; }
            else        { mah = &a1h; mal = &a1l; ak = (j - S0) * KC; bk = bk1 + (j - S0) * KC; }
            tma2d(sb + STG_AH, mah, ak, m0, full);
            tma2d(sb + STG_AL, mal, ak, m0, full);
            tma2d(sb + STG_BH, &bh, bk, n0, full);
            tma2d(sb + STG_BL, &bl, bk, n0, full);
        }
        if (++s == NST) { s = 0; ph ^= 1; }
    }

    // ---------------- epilogue ----------------
    const int mrow = m0 + wm + (lane >> 2);
    const int ncol = n0 + wn + 2 * (lane & 3);

    #pragma unroll
    for (int mi = 0; mi < MI; mi++) {
        #pragma unroll
        for (int ni = 0; ni < 4; ni++) {
            const int n = ncol + ni * 8;
            const int ma = mrow + mi * 16;
            const int mb = ma + 8;
            if (MODE == 1 && n >= ONN_) continue;
            const float2 bv = __ldg(reinterpret_cast<const float2*>(bias + n));
            float v00 = acc[mi][ni][0] + bv.x;
            float v01 = acc[mi][ni][1] + bv.y;
            float v10 = acc[mi][ni][2] + bv.x;
            float v11 = acc[mi][ni][3] + bv.y;
            if (MODE == 0) {
                v00 = v00 > 0.f ? v00 : 0.f;
                v01 = v01 > 0.f ? v01 : 0.f;
                v10 = v10 > 0.f ? v10 : 0.f;
                v11 = v11 > 0.f ? v11 : 0.f;
                __nv_bfloat16 h00 = __float2bfloat16_rn(v00);
                __nv_bfloat16 h01 = __float2bfloat16_rn(v01);
                __nv_bfloat16 h10 = __float2bfloat16_rn(v10);
                __nv_bfloat16 h11 = __float2bfloat16_rn(v11);
                __nv_bfloat16 l00 = __float2bfloat16_rn(v00 - __bfloat162float(h00));
                __nv_bfloat16 l01 = __float2bfloat16_rn(v01 - __bfloat162float(h01));
                __nv_bfloat16 l10 = __float2bfloat16_rn(v10 - __bfloat162float(h10));
                __nv_bfloat16 l11 = __float2bfloat16_rn(v11 - __bfloat162float(h11));
                uint32_t ph0 = (uint32_t)__bfloat16_as_ushort(h00) | ((uint32_t)__bfloat16_as_ushort(h01) << 16);
                uint32_t ph1 = (uint32_t)__bfloat16_as_ushort(h10) | ((uint32_t)__bfloat16_as_ushort(h11) << 16);
                uint32_t pl0 = (uint32_t)__bfloat16_as_ushort(l00) | ((uint32_t)__bfloat16_as_ushort(l01) << 16);
                uint32_t pl1 = (uint32_t)__bfloat16_as_ushort(l10) | ((uint32_t)__bfloat16_as_ushort(l11) << 16);
                *reinterpret_cast<uint32_t*>(g_h1h + (size_t)ma * HID_ + n) = ph0;
                *reinterpret_cast<uint32_t*>(g_h1h + (size_t)mb * HID_ + n) = ph1;
                *reinterpret_cast<uint32_t*>(g_h1l + (size_t)ma * HID_ + n) = pl0;
                *reinterpret_cast<uint32_t*>(g_h1l + (size_t)mb * HID_ + n) = pl1;
            } else {
                float2 o0 = { v00, v01 };
                float2 o1 = { v10, v11 };
                *reinterpret_cast<float2*>(outp + (size_t)ma * ONN_ + n) = o0;
                *reinterpret_cast<float2*>(outp + (size_t)mb * ONN_ + n) = o1;
            }
        }
    }
}

// ---------------- host side ---------------------
typedef CUresult (*PFN_tmap)(CUtensorMap*, CUtensorMapDataType, cuuint32_t, void*,
                             const cuuint64_t*, const cuuint64_t*, const cuuint32_t*,
                             const cuuint32_t*, CUtensorMapInterleave, CUtensorMapSwizzle,
                             CUtensorMapL2promotion, CUtensorMapFloatOOBfill);

static void mk2d(PFN_tmap f, CUtensorMap* m, void* p,
                 unsigned long long k, unsigned long long rows, unsigned box1)
{
    cuuint64_t dims[2] = { k, rows };
    cuuint64_t str[1]  = { k * 2 };        // row stride in bytes (bf16)
    cuuint32_t box[2]  = { 64u, box1 };
    cuuint32_t es[2]   = { 1u, 1u };
    f(m, CU_TENSOR_MAP_DATA_TYPE_BFLOAT16, 2, p, dims, str, box, es,
      CU_TENSOR_MAP_INTERLEAVE_NONE, CU_TENSOR_MAP_SWIZZLE_128B,
      CU_TENSOR_MAP_L2_PROMOTION_L2_128B, CU_TENSOR_MAP_FLOAT_OOB_FILL_NONE);
}

extern "C" void kernel_launch(void* const* d_in, const int* in_sizes, int n_in,
                              void* d_out, int out_size)
{
    const float* x  = (const float*)d_in[0];
    const float* W1 = (const float*)d_in[1];
    const float* b1 = (const float*)d_in[2];
    const float* W2 = (const float*)d_in[3];
    const float* b2 = (const float*)d_in[4];
    float* out = (float*)d_out;

    void *xh, *xl, *w1h, *w1l, *w2h, *w2l, *h1h, *h1l;
    cudaGetSymbolAddress(&xh,  g_xh);  cudaGetSymbolAddress(&xl,  g_xl);
    cudaGetSymbolAddress(&w1h, g_w1h); cudaGetSymbolAddress(&w1l, g_w1l);
    cudaGetSymbolAddress(&w2h, g_w2h); cudaGetSymbolAddress(&w2l, g_w2l);
    cudaGetSymbolAddress(&h1h, g_h1h); cudaGetSymbolAddress(&h1l, g_h1l);

    // conversions (fp32 -> bf16 hi/lo)
    {
        size_t n4x  = (size_t)MB_ * DIN_ / 4;
        size_t n4w1 = (size_t)HID_ * DIN_ / 4;
        size_t n4w2 = (size_t)ONN_ * K2_ / 4;
        split_fp32<<<(unsigned)((n4x  + 255) / 256), 256>>>(x,  (__nv_bfloat16*)xh,  (__nv_bfloat16*)xl,  n4x);
        split_fp32<<<(unsigned)((n4w1 + 255) / 256), 256>>>(W1, (__nv_bfloat16*)w1h, (__nv_bfloat16*)w1l, n4w1);
        split_fp32<<<(unsigned)((n4w2 + 255) / 256), 256>>>(W2, (__nv_bfloat16*)w2h, (__nv_bfloat16*)w2l, n4w2);
    }

    PFN_tmap enc = nullptr;
    cudaDriverEntryPointQueryResult qr;
    cudaGetDriverEntryPoint("cuTensorMapEncodeTiled", (void**)&enc,
                            cudaEnableDefault, &qr);

    CUtensorMap m_xh128, m_xl128, m_xh64, m_xl64;
    CUtensorMap m_h1h64, m_h1l64, m_w1h, m_w1l, m_w2h, m_w2l;
    mk2d(enc, &m_xh128, xh,  DIN_, MB_,  128);
    mk2d(enc, &m_xl128, xl,  DIN_, MB_,  128);
    mk2d(enc, &m_xh64,  xh,  DIN_, MB_,  64);
    mk2d(enc, &m_xl64,  xl,  DIN_, MB_,  64);
    mk2d(enc, &m_h1h64, h1h, HID_, MB_,  64);
    mk2d(enc, &m_h1l64, h1l, HID_, MB_,  64);
    mk2d(enc, &m_w1h,   w1h, DIN_, HID_, 64);
    mk2d(enc, &m_w1l,   w1l, DIN_, HID_, 64);
    mk2d(enc, &m_w2h,   w2h, K2_,  ONN_, 64);
    mk2d(enc, &m_w2l,   w2l, K2_,  ONN_, 64);

    // GEMM1: TBM=128, BN=64, NSTAGE=2  -> stage 48KB, smem/CTA 97KB, 2 CTA/SM
    // GEMM2: TBM=64,  BN=64, NSTAGE=3  -> stage 32KB, smem/CTA 97KB, 2 CTA/SM
    const int smem1 = STAGE0_OFF + 2 * (2 * 128 * 128 + 2 * 64 * 128);   // 99328
    const int smem2 = STAGE0_OFF + 3 * (2 * 64 * 128 + 2 * 64 * 128);    // 99328
    cudaFuncSetAttribute(gemm_hmma<0,128,64,2>, cudaFuncAttributeMaxDynamicSharedMemorySize, smem1);
    cudaFuncSetAttribute(gemm_hmma<1,64,64,3>,  cudaFuncAttributeMaxDynamicSharedMemorySize, smem2);

    // GEMM1: h1 = relu(x @ W1^T + b1)
    dim3 g1(MB_ / 128, HID_ / 64);   // (32, 256)
    gemm_hmma<0,128,64,2><<<g1, 128, smem1>>>(m_xh128, m_xl128, m_xh128, m_xl128,
                                              m_w1h, m_w1l, DIN_, 0, 0, b1, nullptr);

    // GEMM2: out = [x, h1] @ W2^T + b2
    dim3 g2(MB_ / 64, (ONN_ + 63) / 64);   // (64, 16)
    gemm_hmma<1,64,64,3><<<g2, 128, smem2>>>(m_xh64, m_xl64, m_h1h64, m_h1l64,
                                             m_w2h, m_w2l, DIN_, HID_, DIN_, b2, out);
}

// round 7
// speedup vs baseline: 2.8064x; 1.0089x over previous
#include <cuda_runtime.h>
#include <cuda_bf16.h>
#include <cuda.h>
#include <cstdint>
#include <cstddef>

// ---------------- problem dims ----------------
#define MB_   4096
#define DIN_  4096
#define HID_  16384
#define ONN_  1000
#define K2_   (DIN_ + HID_)

#define KC 64                   // bf16 K per stage (128 B rows = SW128 atom)
#define STAGE0_OFF 1024

// bf16 split scratch (static device arrays — no allocation)
__device__ __align__(1024) __nv_bfloat16 g_xh [(size_t)MB_ * DIN_];
__device__ __align__(1024) __nv_bfloat16 g_xl [(size_t)MB_ * DIN_];
__device__ __align__(1024) __nv_bfloat16 g_w1h[(size_t)HID_ * DIN_];
__device__ __align__(1024) __nv_bfloat16 g_w1l[(size_t)HID_ * DIN_];
__device__ __align__(1024) __nv_bfloat16 g_w2h[(size_t)ONN_ * K2_];
__device__ __align__(1024) __nv_bfloat16 g_w2l[(size_t)ONN_ * K2_];
__device__ __align__(1024) __nv_bfloat16 g_h1h[(size_t)MB_ * HID_];
__device__ __align__(1024) __nv_bfloat16 g_h1l[(size_t)MB_ * HID_];

// ---------------- PTX helpers ------------------
__device__ __forceinline__ uint32_t smem_u32(const void* p) {
    uint32_t a;
    asm("{ .reg .u64 t; cvta.to.shared.u64 t, %1; cvt.u32.u64 %0, t; }"
        : "=r"(a) : "l"(p));
    return a;
}

#define MBARRIER_INIT(addr, cnt) \
    asm volatile("mbarrier.init.shared.b64 [%0], %1;" :: "r"(addr), "r"(cnt) : "memory")

#define MBARRIER_EXPECT_TX(addr, bytes) \
    asm volatile("mbarrier.arrive.expect_tx.shared.b64 _, [%0], %1;" \
                 :: "r"(addr), "r"(bytes) : "memory")

#define MBARRIER_ARRIVE(addr) \
    asm volatile("mbarrier.arrive.shared.b64 _, [%0];" :: "r"(addr) : "memory")

#define MBARRIER_WAIT_PARITY(addr, parity) do {                                   \
    uint32_t _m = (addr); uint32_t _p = (parity); uint32_t _d;                    \
    asm volatile("{ .reg .pred p; mbarrier.try_wait.parity.acquire.cta.shared::cta.b64 p, [%1], %2; selp.b32 %0, 1, 0, p; }" \
        : "=r"(_d) : "r"(_m), "r"(_p) : "memory");                                \
    if (!_d) {                                                                    \
        asm volatile("{ .reg .pred P1; WL_%=: mbarrier.try_wait.parity.acquire.cta.shared::cta.b64 P1, [%0], %1, 0x989680; @P1 bra.uni WD_%=; bra.uni WL_%=; WD_%=: }" \
            :: "r"(_m), "r"(_p) : "memory");                                      \
    }                                                                             \
} while (0)

__device__ __forceinline__ void tma2d(uint32_t dst, const CUtensorMap* m,
                                      int cx, int cy, uint32_t mbar) {
    asm volatile(
        "cp.async.bulk.tensor.2d.shared::cta.global.tile.mbarrier::complete_tx::bytes "
        "[%0], [%1, {%2, %3}], [%4];"
        :: "r"(dst), "l"(m), "r"(cx), "r"(cy), "r"(mbar) : "memory");
}

#define FENCE_PROXY_ASYNC() asm volatile("fence.proxy.async.shared::cta;" ::: "memory")

__device__ __forceinline__ void ldsm4(uint32_t* r, uint32_t addr) {
    asm volatile("ldmatrix.sync.aligned.m8n8.x4.shared.b16 {%0,%1,%2,%3}, [%4];"
                 : "=r"(r[0]), "=r"(r[1]), "=r"(r[2]), "=r"(r[3]) : "r"(addr));
}

__device__ __forceinline__ void mma16816(float* c, const uint32_t* a, uint32_t b0, uint32_t b1) {
    asm volatile(
        "mma.sync.aligned.m16n8k16.row.col.f32.bf16.bf16.f32 "
        "{%0,%1,%2,%3}, {%4,%5,%6,%7}, {%8,%9}, {%0,%1,%2,%3};"
        : "+f"(c[0]), "+f"(c[1]), "+f"(c[2]), "+f"(c[3])
        : "r"(a[0]), "r"(a[1]), "r"(a[2]), "r"(a[3]), "r"(b0), "r"(b1));
}

// ---------------- split conversion --------------
__global__ void split_fp32(const float* __restrict__ src,
                           __nv_bfloat16* __restrict__ hi,
                           __nv_bfloat16* __restrict__ lo, size_t n4)
{
    size_t i = (size_t)blockIdx.x * blockDim.x + threadIdx.x;
    if (i >= n4) return;
    float4 v = reinterpret_cast<const float4*>(src)[i];
    __nv_bfloat16 h0 = __float2bfloat16_rn(v.x);
    __nv_bfloat16 h1 = __float2bfloat16_rn(v.y);
    __nv_bfloat16 h2 = __float2bfloat16_rn(v.z);
    __nv_bfloat16 h3 = __float2bfloat16_rn(v.w);
    __nv_bfloat16 l0 = __float2bfloat16_rn(v.x - __bfloat162float(h0));
    __nv_bfloat16 l1 = __float2bfloat16_rn(v.y - __bfloat162float(h1));
    __nv_bfloat16 l2 = __float2bfloat16_rn(v.z - __bfloat162float(h2));
    __nv_bfloat16 l3 = __float2bfloat16_rn(v.w - __bfloat162float(h3));
    uint2 ph, pl;
    ph.x = (uint32_t)__bfloat16_as_ushort(h0) | ((uint32_t)__bfloat16_as_ushort(h1) << 16);
    ph.y = (uint32_t)__bfloat16_as_ushort(h2) | ((uint32_t)__bfloat16_as_ushort(h3) << 16);
    pl.x = (uint32_t)__bfloat16_as_ushort(l0) | ((uint32_t)__bfloat16_as_ushort(l1) << 16);
    pl.y = (uint32_t)__bfloat16_as_ushort(l2) | ((uint32_t)__bfloat16_as_ushort(l3) << 16);
    reinterpret_cast<uint2*>(hi)[i] = ph;
    reinterpret_cast<uint2*>(lo)[i] = pl;
}

// ======================= GEMM1: BM=128 x BN=256, warp tile 64x64 =============
// h1 = relu(x @ W1^T + b1), output split to bf16 hi/lo.
__global__ __launch_bounds__(256, 1)
void gemm1_hmma(const __grid_constant__ CUtensorMap ah_m,
                const __grid_constant__ CUtensorMap al_m,
                const __grid_constant__ CUtensorMap bh_m,
                const __grid_constant__ CUtensorMap bl_m,
                const float* __restrict__ bias)
{
    constexpr int NST = 2;
    constexpr uint32_t STG_AH = 0;
    constexpr uint32_t STG_AL = 16384;       // 128*128
    constexpr uint32_t STG_BH = 32768;
    constexpr uint32_t STG_BL = 65536;       // BH is 256*128 = 32768
    constexpr uint32_t STAGE_SZ = 98304;

    extern __shared__ __align__(1024) char smem[];
    const uint32_t sbase = smem_u32(smem);

    const int tid  = threadIdx.x;
    const int lane = tid & 31;
    const int wid  = tid >> 5;
    const int wm   = (wid & 1) * 64;
    const int wn   = (wid >> 1) * 64;

    if (tid == 0) {
        #pragma unroll
        for (int s = 0; s < NST; s++) {
            MBARRIER_INIT(sbase + 8u * s, 1);
            MBARRIER_INIT(sbase + 64u + 8u * s, 8);
        }
        FENCE_PROXY_ASYNC();
    }
    __syncthreads();

    const int m0 = blockIdx.x * 128;
    const int n0 = blockIdx.y * 256;
    const int T  = DIN_ / KC;    // 64

    const uint32_t rowoff = (uint32_t)(lane & 15) * 128u;
    const uint32_t hi4 = (uint32_t)(lane >> 4);
    const uint32_t lo7 = (uint32_t)(lane & 7);
    uint32_t cb[4];
    #pragma unroll
    for (int ks = 0; ks < 4; ks++)
        cb[ks] = (((2u * ks + hi4) ^ lo7) << 4);

    float acc[4][8][4];
    #pragma unroll
    for (int mi = 0; mi < 4; mi++)
        #pragma unroll
        for (int ni = 0; ni < 8; ni++)
            #pragma unroll
            for (int q = 0; q < 4; q++) acc[mi][ni][q] = 0.f;

    if (tid == 0) {
        #pragma unroll
        for (int j = 0; j < NST; j++) {
            const uint32_t full = sbase + 8u * j;
            MBARRIER_EXPECT_TX(full, STAGE_SZ);
            const uint32_t sb = sbase + STAGE0_OFF + (uint32_t)j * STAGE_SZ;
            tma2d(sb + STG_AH, &ah_m, j * KC, m0, full);
            tma2d(sb + STG_AL, &al_m, j * KC, m0, full);
            tma2d(sb + STG_BH, &bh_m, j * KC, n0, full);
            tma2d(sb + STG_BL, &bl_m, j * KC, n0, full);
        }
    }

    int s = 0, ph = 0;
    #pragma unroll 1
    for (int i = 0; i < T; i++) {
        MBARRIER_WAIT_PARITY(sbase + 8u * s, (uint32_t)ph);

        const uint32_t sb  = sbase + STAGE0_OFF + (uint32_t)s * STAGE_SZ;
        const uint32_t aHb = sb + STG_AH + (uint32_t)wm * 128u + rowoff;
        const uint32_t aLb = sb + STG_AL + (uint32_t)wm * 128u + rowoff;
        const uint32_t bHb = sb + STG_BH + (uint32_t)wn * 128u + rowoff;
        const uint32_t bLb = sb + STG_BL + (uint32_t)wn * 128u + rowoff;

        #pragma unroll
        for (int ks = 0; ks < 4; ks++) {
            uint32_t ah[4][4], al[4][4], bb[4][4];
            #pragma unroll
            for (int mi = 0; mi < 4; mi++)
                ldsm4(ah[mi], aHb + (uint32_t)mi * (16u * 128u) + cb[ks]);
            #pragma unroll
            for (int mi = 0; mi < 4; mi++)
                ldsm4(al[mi], aLb + (uint32_t)mi * (16u * 128u) + cb[ks]);
            #pragma unroll
            for (int nj = 0; nj < 4; nj++)
                ldsm4(bb[nj], bHb + (uint32_t)nj * (16u * 128u) + cb[ks]);

            // pass1: Ah x Bh ; pass2: Al x Bh
            #pragma unroll
            for (int mi = 0; mi < 4; mi++)
                #pragma unroll
                for (int ni = 0; ni < 8; ni++) {
                    const uint32_t b0 = bb[ni >> 1][ni & 1];
                    const uint32_t b1 = bb[ni >> 1][(ni & 1) + 2];
                    mma16816(acc[mi][ni], ah[mi], b0, b1);
                }
            #pragma unroll
            for (int mi = 0; mi < 4; mi++)
                #pragma unroll
                for (int ni = 0; ni < 8; ni++) {
                    const uint32_t b0 = bb[ni >> 1][ni & 1];
                    const uint32_t b1 = bb[ni >> 1][(ni & 1) + 2];
                    mma16816(acc[mi][ni], al[mi], b0, b1);
                }
            // pass3: Ah x Bl
            #pragma unroll
            for (int nj = 0; nj < 4; nj++)
                ldsm4(bb[nj], bLb + (uint32_t)nj * (16u * 128u) + cb[ks]);
            #pragma unroll
            for (int mi = 0; mi < 4; mi++)
                #pragma unroll
                for (int ni = 0; ni < 8; ni++) {
                    const uint32_t b0 = bb[ni >> 1][ni & 1];
                    const uint32_t b1 = bb[ni >> 1][(ni & 1) + 2];
                    mma16816(acc[mi][ni], ah[mi], b0, b1);
                }
        }

        if (lane == 0) MBARRIER_ARRIVE(sbase + 64u + 8u * s);

        const int j = i + NST;
        if (tid == 0 && j < T) {
            MBARRIER_WAIT_PARITY(sbase + 64u + 8u * s, (uint32_t)ph);
            const uint32_t full = sbase + 8u * s;
            MBARRIER_EXPECT_TX(full, STAGE_SZ);
            tma2d(sb + STG_AH, &ah_m, j * KC, m0, full);
            tma2d(sb + STG_AL, &al_m, j * KC, m0, full);
            tma2d(sb + STG_BH, &bh_m, j * KC, n0, full);
            tma2d(sb + STG_BL, &bl_m, j * KC, n0, full);
        }
        if (++s == NST) { s = 0; ph ^= 1; }
    }

    // epilogue: bias + relu + bf16 hi/lo split
    const int mrow = m0 + wm + (lane >> 2);
    const int ncol = n0 + wn + 2 * (lane & 3);

    #pragma unroll
    for (int mi = 0; mi < 4; mi++) {
        #pragma unroll
        for (int ni = 0; ni < 8; ni++) {
            const int n = ncol + ni * 8;
            const int ma = mrow + mi * 16;
            const int mb = ma + 8;
            const float2 bv = __ldg(reinterpret_cast<const float2*>(bias + n));
            float v00 = acc[mi][ni][0] + bv.x;
            float v01 = acc[mi][ni][1] + bv.y;
            float v10 = acc[mi][ni][2] + bv.x;
            float v11 = acc[mi][ni][3] + bv.y;
            v00 = v00 > 0.f ? v00 : 0.f;
            v01 = v01 > 0.f ? v01 : 0.f;
            v10 = v10 > 0.f ? v10 : 0.f;
            v11 = v11 > 0.f ? v11 : 0.f;
            __nv_bfloat16 h00 = __float2bfloat16_rn(v00);
            __nv_bfloat16 h01 = __float2bfloat16_rn(v01);
            __nv_bfloat16 h10 = __float2bfloat16_rn(v10);
            __nv_bfloat16 h11 = __float2bfloat16_rn(v11);
            __nv_bfloat16 l00 = __float2bfloat16_rn(v00 - __bfloat162float(h00));
            __nv_bfloat16 l01 = __float2bfloat16_rn(v01 - __bfloat162float(h01));
            __nv_bfloat16 l10 = __float2bfloat16_rn(v10 - __bfloat162float(h10));
            __nv_bfloat16 l11 = __float2bfloat16_rn(v11 - __bfloat162float(h11));
            uint32_t p0 = (uint32_t)__bfloat16_as_ushort(h00) | ((uint32_t)__bfloat16_as_ushort(h01) << 16);
            uint32_t p1 = (uint32_t)__bfloat16_as_ushort(h10) | ((uint32_t)__bfloat16_as_ushort(h11) << 16);
            uint32_t q0 = (uint32_t)__bfloat16_as_ushort(l00) | ((uint32_t)__bfloat16_as_ushort(l01) << 16);
            uint32_t q1 = (uint32_t)__bfloat16_as_ushort(l10) | ((uint32_t)__bfloat16_as_ushort(l11) << 16);
            *reinterpret_cast<uint32_t*>(g_h1h + (size_t)ma * HID_ + n) = p0;
            *reinterpret_cast<uint32_t*>(g_h1h + (size_t)mb * HID_ + n) = p1;
            *reinterpret_cast<uint32_t*>(g_h1l + (size_t)ma * HID_ + n) = q0;
            *reinterpret_cast<uint32_t*>(g_h1l + (size_t)mb * HID_ + n) = q1;
        }
    }
}

// ======================= GEMM2: TBM=64 x BN=128 (R4 config) ==================
__global__ __launch_bounds__(256, 1)
void gemm2_hmma(const __grid_constant__ CUtensorMap a0h,
                const __grid_constant__ CUtensorMap a0l,
                const __grid_constant__ CUtensorMap a1h,
                const __grid_constant__ CUtensorMap a1l,
                const __grid_constant__ CUtensorMap bh,
                const __grid_constant__ CUtensorMap bl,
                const float* __restrict__ bias,
                float* __restrict__ outp)
{
    constexpr int NST = 3;
    constexpr int TBM = 64;
    constexpr int MI = 2;
    constexpr uint32_t ASZ = 8192;
    constexpr uint32_t STG_AH = 0;
    constexpr uint32_t STG_AL = ASZ;
    constexpr uint32_t STG_BH = 2u * ASZ;
    constexpr uint32_t STG_BL = 2u * ASZ + 16384u;
    constexpr uint32_t STAGE_SZ = 2u * ASZ + 32768u;

    extern __shared__ __align__(1024) char smem[];
    const uint32_t sbase = smem_u32(smem);

    const int tid  = threadIdx.x;
    const int lane = tid & 31;
    const int wid  = tid >> 5;
    const int wm   = (wid & 1) * 32;
    const int wn   = (wid >> 1) * 32;

    if (tid == 0) {
        #pragma unroll
        for (int s = 0; s < NST; s++) {
            MBARRIER_INIT(sbase + 8u * s, 1);
            MBARRIER_INIT(sbase + 64u + 8u * s, 8);
        }
        FENCE_PROXY_ASYNC();
    }
    __syncthreads();

    const int m0 = blockIdx.x * TBM;
    const int n0 = blockIdx.y * 128;
    const int S0 = DIN_ / KC;
    const int T  = K2_ / KC;

    const uint32_t rowoff = (uint32_t)(lane & 15) * 128u;
    const uint32_t hi4 = (uint32_t)(lane >> 4);
    const uint32_t lo7 = (uint32_t)(lane & 7);
    uint32_t cb[4];
    #pragma unroll
    for (int ks = 0; ks < 4; ks++)
        cb[ks] = (((2u * ks + hi4) ^ lo7) << 4);

    float acc[MI][4][4];
    #pragma unroll
    for (int mi = 0; mi < MI; mi++)
        #pragma unroll
        for (int ni = 0; ni < 4; ni++)
            #pragma unroll
            for (int q = 0; q < 4; q++) acc[mi][ni][q] = 0.f;

    if (tid == 0) {
        #pragma unroll
        for (int j = 0; j < NST; j++) {
            const uint32_t full = sbase + 8u * j;
            MBARRIER_EXPECT_TX(full, STAGE_SZ);
            const uint32_t sb = sbase + STAGE0_OFF + (uint32_t)j * STAGE_SZ;
            const CUtensorMap *mah, *mal; int ak, bk;
            if (j < S0) { mah = &a0h; mal = &a0l; ak = j * KC; bk = j * KC; }
            else        { mah = &a1h; mal = &a1l; ak = (j - S0) * KC; bk = DIN_ + (j - S0) * KC; }
            tma2d(sb + STG_AH, mah, ak, m0, full);
            tma2d(sb + STG_AL, mal, ak, m0, full);
            tma2d(sb + STG_BH, &bh, bk, n0, full);
            tma2d(sb + STG_BL, &bl, bk, n0, full);
        }
    }

    int s = 0, ph = 0;
    #pragma unroll 1
    for (int i = 0; i < T; i++) {
        MBARRIER_WAIT_PARITY(sbase + 8u * s, (uint32_t)ph);

        const uint32_t sb  = sbase + STAGE0_OFF + (uint32_t)s * STAGE_SZ;
        const uint32_t aHb = sb + STG_AH + (uint32_t)wm * 128u + rowoff;
        const uint32_t aLb = sb + STG_AL + (uint32_t)wm * 128u + rowoff;
        const uint32_t bHb = sb + STG_BH + (uint32_t)wn * 128u + rowoff;
        const uint32_t bLb = sb + STG_BL + (uint32_t)wn * 128u + rowoff;

        #pragma unroll
        for (int ks = 0; ks < 4; ks++) {
            uint32_t ah[MI][4], al[MI][4], bb[2][4];
            #pragma unroll
            for (int mi = 0; mi < MI; mi++)
                ldsm4(ah[mi], aHb + (uint32_t)mi * (16u * 128u) + cb[ks]);
            #pragma unroll
            for (int mi = 0; mi < MI; mi++)
                ldsm4(al[mi], aLb + (uint32_t)mi * (16u * 128u) + cb[ks]);
            #pragma unroll
            for (int nj = 0; nj < 2; nj++)
                ldsm4(bb[nj], bHb + (uint32_t)nj * (16u * 128u) + cb[ks]);

            #pragma unroll
            for (int mi = 0; mi < MI; mi++)
                #pragma unroll
                for (int ni = 0; ni < 4; ni++) {
                    const uint32_t b0 = bb[ni >> 1][ni & 1];
                    const uint32_t b1 = bb[ni >> 1][(ni & 1) + 2];
                    mma16816(acc[mi][ni], ah[mi], b0, b1);
                }
            #pragma unroll
            for (int mi = 0; mi < MI; mi++)
                #pragma unroll
                for (int ni = 0; ni < 4; ni++) {
                    const uint32_t b0 = bb[ni >> 1][ni & 1];
                    const uint32_t b1 = bb[ni >> 1][(ni & 1) + 2];
                    mma16816(acc[mi][ni], al[mi], b0, b1);
                }
            #pragma unroll
            for (int nj = 0; nj < 2; nj++)
                ldsm4(bb[nj], bLb + (uint32_t)nj * (16u * 128u) + cb[ks]);
            #pragma unroll
            for (int mi = 0; mi < MI; mi++)
                #pragma unroll
                for (int ni = 0; ni < 4; ni++) {
                    const uint32_t b0 = bb[ni >> 1][ni & 1];
                    const uint32_t b1 = bb[ni >> 1][(ni & 1) + 2];
                    mma16816(acc[mi][ni], ah[mi], b0, b1);
                }
        }

        if (lane == 0) MBARRIER_ARRIVE(sbase + 64u + 8u * s);

        const int j = i + NST;
        if (tid == 0 && j < T) {
            MBARRIER_WAIT_PARITY(sbase + 64u + 8u * s, (uint32_t)ph);
            const uint32_t full = sbase + 8u * s;
            MBARRIER_EXPECT_TX(full, STAGE_SZ);
            const CUtensorMap *mah, *mal; int ak, bk;
            if (j < S0) { mah = &a0h; mal = &a0l; ak = j * KC; bk = j * KC; }
            else        { mah = &a1h; mal = &a1l; ak = (j - S0) * KC; bk = DIN_ + (j - S0) * KC; }
            tma2d(sb + STG_AH, mah, ak, m0, full);
            tma2d(sb + STG_AL, mal, ak, m0, full);
            tma2d(sb + STG_BH, &bh, bk, n0, full);
            tma2d(sb + STG_BL, &bl, bk, n0, full);
        }
        if (++s == NST) { s = 0; ph ^= 1; }
    }

    const int mrow = m0 + wm + (lane >> 2);
    const int ncol = n0 + wn + 2 * (lane & 3);

    #pragma unroll
    for (int mi = 0; mi < MI; mi++) {
        #pragma unroll
        for (int ni = 0; ni < 4; ni++) {
            const int n = ncol + ni * 8;
            const int ma = mrow + mi * 16;
            const int mb = ma + 8;
            if (n >= ONN_) continue;
            const float2 bv = __ldg(reinterpret_cast<const float2*>(bias + n));
            float2 o0 = { acc[mi][ni][0] + bv.x, acc[mi][ni][1] + bv.y };
            float2 o1 = { acc[mi][ni][2] + bv.x, acc[mi][ni][3] + bv.y };
            *reinterpret_cast<float2*>(outp + (size_t)ma * ONN_ + n) = o0;
            *reinterpret_cast<float2*>(outp + (size_t)mb * ONN_ + n) = o1;
        }
    }
}

// ---------------- host side ---------------------
typedef CUresult (*PFN_tmap)(CUtensorMap*, CUtensorMapDataType, cuuint32_t, void*,
                             const cuuint64_t*, const cuuint64_t*, const cuuint32_t*,
                             const cuuint32_t*, CUtensorMapInterleave, CUtensorMapSwizzle,
                             CUtensorMapL2promotion, CUtensorMapFloatOOBfill);

static void mk2d(PFN_tmap f, CUtensorMap* m, void* p,
                 unsigned long long k, unsigned long long rows, unsigned box1)
{
    cuuint64_t dims[2] = { k, rows };
    cuuint64_t str[1]  = { k * 2 };
    cuuint32_t box[2]  = { 64u, box1 };
    cuuint32_t es[2]   = { 1u, 1u };
    f(m, CU_TENSOR_MAP_DATA_TYPE_BFLOAT16, 2, p, dims, str, box, es,
      CU_TENSOR_MAP_INTERLEAVE_NONE, CU_TENSOR_MAP_SWIZZLE_128B,
      CU_TENSOR_MAP_L2_PROMOTION_L2_128B, CU_TENSOR_MAP_FLOAT_OOB_FILL_NONE);
}

extern "C" void kernel_launch(void* const* d_in, const int* in_sizes, int n_in,
                              void* d_out, int out_size)
{
    const float* x  = (const float*)d_in[0];
    const float* W1 = (const float*)d_in[1];
    const float* b1 = (const float*)d_in[2];
    const float* W2 = (const float*)d_in[3];
    const float* b2 = (const float*)d_in[4];
    float* out = (float*)d_out;

    void *xh, *xl, *w1h, *w1l, *w2h, *w2l, *h1h, *h1l;
    cudaGetSymbolAddress(&xh,  g_xh);  cudaGetSymbolAddress(&xl,  g_xl);
    cudaGetSymbolAddress(&w1h, g_w1h); cudaGetSymbolAddress(&w1l, g_w1l);
    cudaGetSymbolAddress(&w2h, g_w2h); cudaGetSymbolAddress(&w2l, g_w2l);
    cudaGetSymbolAddress(&h1h, g_h1h); cudaGetSymbolAddress(&h1l, g_h1l);

    {
        size_t n4x  = (size_t)MB_ * DIN_ / 4;
        size_t n4w1 = (size_t)HID_ * DIN_ / 4;
        size_t n4w2 = (size_t)ONN_ * K2_ / 4;
        split_fp32<<<(unsigned)((n4x  + 255) / 256), 256>>>(x,  (__nv_bfloat16*)xh,  (__nv_bfloat16*)xl,  n4x);
        split_fp32<<<(unsigned)((n4w1 + 255) / 256), 256>>>(W1, (__nv_bfloat16*)w1h, (__nv_bfloat16*)w1l, n4w1);
        split_fp32<<<(unsigned)((n4w2 + 255) / 256), 256>>>(W2, (__nv_bfloat16*)w2h, (__nv_bfloat16*)w2l, n4w2);
    }

    PFN_tmap enc = nullptr;
    cudaDriverEntryPointQueryResult qr;
    cudaGetDriverEntryPoint("cuTensorMapEncodeTiled", (void**)&enc,
                            cudaEnableDefault, &qr);

    CUtensorMap m_xh128, m_xl128, m_xh64, m_xl64;
    CUtensorMap m_h1h64, m_h1l64, m_w1h, m_w1l, m_w2h, m_w2l;
    mk2d(enc, &m_xh128, xh,  DIN_, MB_,  128);
    mk2d(enc, &m_xl128, xl,  DIN_, MB_,  128);
    mk2d(enc, &m_xh64,  xh,  DIN_, MB_,  64);
    mk2d(enc, &m_xl64,  xl,  DIN_, MB_,  64);
    mk2d(enc, &m_h1h64, h1h, HID_, MB_,  64);
    mk2d(enc, &m_h1l64, h1l, HID_, MB_,  64);
    mk2d(enc, &m_w1h,   w1h, DIN_, HID_, 256);
    mk2d(enc, &m_w1l,   w1l, DIN_, HID_, 256);
    mk2d(enc, &m_w2h,   w2h, K2_,  ONN_, 128);
    mk2d(enc, &m_w2l,   w2l, K2_,  ONN_, 128);

    const int smem1 = STAGE0_OFF + 2 * 98304;                          // 197632
    const int smem2 = STAGE0_OFF + 3 * (2 * 8192 + 32768);             // 148480
    cudaFuncSetAttribute(gemm1_hmma, cudaFuncAttributeMaxDynamicSharedMemorySize, smem1);
    cudaFuncSetAttribute(gemm2_hmma, cudaFuncAttributeMaxDynamicSharedMemorySize, smem2);

    // GEMM1: h1 = relu(x @ W1^T + b1)
    dim3 g1(MB_ / 128, HID_ / 256);   // (32, 64)
    gemm1_hmma<<<g1, 256, smem1>>>(m_xh128, m_xl128, m_w1h, m_w1l, b1);

    // GEMM2: out = [x, h1] @ W2^T + b2
    dim3 g2(MB_ / 64, 8);             // (64, 8)
    gemm2_hmma<<<g2, 256, smem2>>>(m_xh64, m_xl64, m_h1h64, m_h1l64,
                                   m_w2h, m_w2l, b2, out);
}

// round 8
// speedup vs baseline: 4.3056x; 1.5342x over previous
#include <cuda_runtime.h>
#include <cuda_fp16.h>
#include <cuda.h>
#include <cstdint>
#include <cstddef>

// ---------------- problem dims ----------------
#define MB_   4096
#define DIN_  4096
#define HID_  16384
#define ONN_  1000
#define K2_   (DIN_ + HID_)

#define KC 64                   // fp16 K per stage (128 B rows = SW128 atom)
#define STAGE0_OFF 1024

// fp16 scratch (static device arrays — no allocation)
__device__ __align__(1024) __half g_xf [(size_t)MB_ * DIN_];
__device__ __align__(1024) __half g_w1h[(size_t)HID_ * DIN_];
__device__ __align__(1024) __half g_w1l[(size_t)HID_ * DIN_];
__device__ __align__(1024) __half g_w2h[(size_t)ONN_ * K2_];
__device__ __align__(1024) __half g_w2l[(size_t)ONN_ * K2_];
__device__ __align__(1024) __half g_h1 [(size_t)MB_ * HID_];

// ---------------- PTX helpers ------------------
__device__ __forceinline__ uint32_t smem_u32(const void* p) {
    uint32_t a;
    asm("{ .reg .u64 t; cvta.to.shared.u64 t, %1; cvt.u32.u64 %0, t; }"
        : "=r"(a) : "l"(p));
    return a;
}

#define MBARRIER_INIT(addr, cnt) \
    asm volatile("mbarrier.init.shared.b64 [%0], %1;" :: "r"(addr), "r"(cnt) : "memory")

#define MBARRIER_EXPECT_TX(addr, bytes) \
    asm volatile("mbarrier.arrive.expect_tx.shared.b64 _, [%0], %1;" \
                 :: "r"(addr), "r"(bytes) : "memory")

#define MBARRIER_ARRIVE(addr) \
    asm volatile("mbarrier.arrive.shared.b64 _, [%0];" :: "r"(addr) : "memory")

#define MBARRIER_WAIT_PARITY(addr, parity) do {                                   \
    uint32_t _m = (addr); uint32_t _p = (parity); uint32_t _d;                    \
    asm volatile("{ .reg .pred p; mbarrier.try_wait.parity.acquire.cta.shared::cta.b64 p, [%1], %2; selp.b32 %0, 1, 0, p; }" \
        : "=r"(_d) : "r"(_m), "r"(_p) : "memory");                                \
    if (!_d) {                                                                    \
        asm volatile("{ .reg .pred P1; WL_%=: mbarrier.try_wait.parity.acquire.cta.shared::cta.b64 P1, [%0], %1, 0x989680; @P1 bra.uni WD_%=; bra.uni WL_%=; WD_%=: }" \
            :: "r"(_m), "r"(_p) : "memory");                                      \
    }                                                                             \
} while (0)

__device__ __forceinline__ void tma2d(uint32_t dst, const CUtensorMap* m,
                                      int cx, int cy, uint32_t mbar) {
    asm volatile(
        "cp.async.bulk.tensor.2d.shared::cta.global.tile.mbarrier::complete_tx::bytes "
        "[%0], [%1, {%2, %3}], [%4];"
        :: "r"(dst), "l"(m), "r"(cx), "r"(cy), "r"(mbar) : "memory");
}

#define FENCE_PROXY_ASYNC() asm volatile("fence.proxy.async.shared::cta;" ::: "memory")

__device__ __forceinline__ void ldsm4(uint32_t* r, uint32_t addr) {
    asm volatile("ldmatrix.sync.aligned.m8n8.x4.shared.b16 {%0,%1,%2,%3}, [%4];"
                 : "=r"(r[0]), "=r"(r[1]), "=r"(r[2]), "=r"(r[3]) : "r"(addr));
}

__device__ __forceinline__ void mma16816(float* c, const uint32_t* a, uint32_t b0, uint32_t b1) {
    asm volatile(
        "mma.sync.aligned.m16n8k16.row.col.f32.f16.f16.f32 "
        "{%0,%1,%2,%3}, {%4,%5,%6,%7}, {%8,%9}, {%0,%1,%2,%3};"
        : "+f"(c[0]), "+f"(c[1]), "+f"(c[2]), "+f"(c[3])
        : "r"(a[0]), "r"(a[1]), "r"(a[2]), "r"(a[3]), "r"(b0), "r"(b1));
}

// ---------------- conversions --------------
__global__ void conv_f16(const float* __restrict__ src,
                         __half* __restrict__ dst, size_t n4)
{
    size_t i = (size_t)blockIdx.x * blockDim.x + threadIdx.x;
    if (i >= n4) return;
    float4 v = reinterpret_cast<const float4*>(src)[i];
    __half h0 = __float2half_rn(v.x);
    __half h1 = __float2half_rn(v.y);
    __half h2 = __float2half_rn(v.z);
    __half h3 = __float2half_rn(v.w);
    uint2 p;
    p.x = (uint32_t)__half_as_ushort(h0) | ((uint32_t)__half_as_ushort(h1) << 16);
    p.y = (uint32_t)__half_as_ushort(h2) | ((uint32_t)__half_as_ushort(h3) << 16);
    reinterpret_cast<uint2*>(dst)[i] = p;
}

__global__ void split_f16(const float* __restrict__ src,
                          __half* __restrict__ hi,
                          __half* __restrict__ lo, size_t n4)
{
    size_t i = (size_t)blockIdx.x * blockDim.x + threadIdx.x;
    if (i >= n4) return;
    float4 v = reinterpret_cast<const float4*>(src)[i];
    __half h0 = __float2half_rn(v.x);
    __half h1 = __float2half_rn(v.y);
    __half h2 = __float2half_rn(v.z);
    __half h3 = __float2half_rn(v.w);
    __half l0 = __float2half_rn(v.x - __half2float(h0));
    __half l1 = __float2half_rn(v.y - __half2float(h1));
    __half l2 = __float2half_rn(v.z - __half2float(h2));
    __half l3 = __float2half_rn(v.w - __half2float(h3));
    uint2 ph, pl;
    ph.x = (uint32_t)__half_as_ushort(h0) | ((uint32_t)__half_as_ushort(h1) << 16);
    ph.y = (uint32_t)__half_as_ushort(h2) | ((uint32_t)__half_as_ushort(h3) << 16);
    pl.x = (uint32_t)__half_as_ushort(l0) | ((uint32_t)__half_as_ushort(l1) << 16);
    pl.y = (uint32_t)__half_as_ushort(l2) | ((uint32_t)__half_as_ushort(l3) << 16);
    reinterpret_cast<uint2*>(hi)[i] = ph;
    reinterpret_cast<uint2*>(lo)[i] = pl;
}

// ======================= GEMM1: BM=128 x BN=256, warp tile 64x64 =============
// h1 = relu(x_f16 @ (W1h+W1l)^T + b1) -> fp16
__global__ __launch_bounds__(256, 1)
void gemm1_hmma(const __grid_constant__ CUtensorMap a_m,
                const __grid_constant__ CUtensorMap bh_m,
                const __grid_constant__ CUtensorMap bl_m,
                const float* __restrict__ bias)
{
    constexpr int NST = 2;
    constexpr uint32_t STG_A  = 0;
    constexpr uint32_t STG_BH = 16384;       // A is 128*128
    constexpr uint32_t STG_BL = 49152;       // BH is 256*128 = 32768
    constexpr uint32_t STAGE_SZ = 81920;

    extern __shared__ __align__(1024) char smem[];
    const uint32_t sbase = smem_u32(smem);

    const int tid  = threadIdx.x;
    const int lane = tid & 31;
    const int wid  = tid >> 5;
    const int wm   = (wid & 1) * 64;
    const int wn   = (wid >> 1) * 64;

    if (tid == 0) {
        #pragma unroll
        for (int s = 0; s < NST; s++) {
            MBARRIER_INIT(sbase + 8u * s, 1);
            MBARRIER_INIT(sbase + 64u + 8u * s, 8);
        }
        FENCE_PROXY_ASYNC();
    }
    __syncthreads();

    const int m0 = blockIdx.x * 128;
    const int n0 = blockIdx.y * 256;
    const int T  = DIN_ / KC;    // 64

    const uint32_t rowoff = (uint32_t)(lane & 15) * 128u;
    const uint32_t hi4 = (uint32_t)(lane >> 4);
    const uint32_t lo7 = (uint32_t)(lane & 7);
    uint32_t cb[4];
    #pragma unroll
    for (int ks = 0; ks < 4; ks++)
        cb[ks] = (((2u * ks + hi4) ^ lo7) << 4);

    float acc[4][8][4];
    #pragma unroll
    for (int mi = 0; mi < 4; mi++)
        #pragma unroll
        for (int ni = 0; ni < 8; ni++)
            #pragma unroll
            for (int q = 0; q < 4; q++) acc[mi][ni][q] = 0.f;

    if (tid == 0) {
        #pragma unroll
        for (int j = 0; j < NST; j++) {
            const uint32_t full = sbase + 8u * j;
            MBARRIER_EXPECT_TX(full, STAGE_SZ);
            const uint32_t sb = sbase + STAGE0_OFF + (uint32_t)j * STAGE_SZ;
            tma2d(sb + STG_A,  &a_m,  j * KC, m0, full);
            tma2d(sb + STG_BH, &bh_m, j * KC, n0, full);
            tma2d(sb + STG_BL, &bl_m, j * KC, n0, full);
        }
    }

    int s = 0, ph = 0;
    #pragma unroll 1
    for (int i = 0; i < T; i++) {
        MBARRIER_WAIT_PARITY(sbase + 8u * s, (uint32_t)ph);

        const uint32_t sb  = sbase + STAGE0_OFF + (uint32_t)s * STAGE_SZ;
        const uint32_t aB  = sb + STG_A  + (uint32_t)wm * 128u + rowoff;
        const uint32_t bHb = sb + STG_BH + (uint32_t)wn * 128u + rowoff;
        const uint32_t bLb = sb + STG_BL + (uint32_t)wn * 128u + rowoff;

        #pragma unroll
        for (int ks = 0; ks < 4; ks++) {
            uint32_t aa[4][4], bb[4][4];
            #pragma unroll
            for (int mi = 0; mi < 4; mi++)
                ldsm4(aa[mi], aB + (uint32_t)mi * (16u * 128u) + cb[ks]);
            #pragma unroll
            for (int nj = 0; nj < 4; nj++)
                ldsm4(bb[nj], bHb + (uint32_t)nj * (16u * 128u) + cb[ks]);

            // pass1: A x Bh
            #pragma unroll
            for (int mi = 0; mi < 4; mi++)
                #pragma unroll
                for (int ni = 0; ni < 8; ni++) {
                    const uint32_t b0 = bb[ni >> 1][ni & 1];
                    const uint32_t b1 = bb[ni >> 1][(ni & 1) + 2];
                    mma16816(acc[mi][ni], aa[mi], b0, b1);
                }
            // pass2: A x Bl
            #pragma unroll
            for (int nj = 0; nj < 4; nj++)
                ldsm4(bb[nj], bLb + (uint32_t)nj * (16u * 128u) + cb[ks]);
            #pragma unroll
            for (int mi = 0; mi < 4; mi++)
                #pragma unroll
                for (int ni = 0; ni < 8; ni++) {
                    const uint32_t b0 = bb[ni >> 1][ni & 1];
                    const uint32_t b1 = bb[ni >> 1][(ni & 1) + 2];
                    mma16816(acc[mi][ni], aa[mi], b0, b1);
                }
        }

        if (lane == 0) MBARRIER_ARRIVE(sbase + 64u + 8u * s);

        const int j = i + NST;
        if (tid == 0 && j < T) {
            MBARRIER_WAIT_PARITY(sbase + 64u + 8u * s, (uint32_t)ph);
            const uint32_t full = sbase + 8u * s;
            MBARRIER_EXPECT_TX(full, STAGE_SZ);
            tma2d(sb + STG_A,  &a_m,  j * KC, m0, full);
            tma2d(sb + STG_BH, &bh_m, j * KC, n0, full);
            tma2d(sb + STG_BL, &bl_m, j * KC, n0, full);
        }
        if (++s == NST) { s = 0; ph ^= 1; }
    }

    // epilogue: bias + relu -> fp16
    const int mrow = m0 + wm + (lane >> 2);
    const int ncol = n0 + wn + 2 * (lane & 3);

    #pragma unroll
    for (int mi = 0; mi < 4; mi++) {
        #pragma unroll
        for (int ni = 0; ni < 8; ni++) {
            const int n = ncol + ni * 8;
            const int ma = mrow + mi * 16;
            const int mb = ma + 8;
            const float2 bv = __ldg(reinterpret_cast<const float2*>(bias + n));
            float v00 = acc[mi][ni][0] + bv.x;
            float v01 = acc[mi][ni][1] + bv.y;
            float v10 = acc[mi][ni][2] + bv.x;
            float v11 = acc[mi][ni][3] + bv.y;
            v00 = v00 > 0.f ? v00 : 0.f;
            v01 = v01 > 0.f ? v01 : 0.f;
            v10 = v10 > 0.f ? v10 : 0.f;
            v11 = v11 > 0.f ? v11 : 0.f;
            uint32_t p0 = (uint32_t)__half_as_ushort(__float2half_rn(v00))
                        | ((uint32_t)__half_as_ushort(__float2half_rn(v01)) << 16);
            uint32_t p1 = (uint32_t)__half_as_ushort(__float2half_rn(v10))
                        | ((uint32_t)__half_as_ushort(__float2half_rn(v11)) << 16);
            *reinterpret_cast<uint32_t*>(g_h1 + (size_t)ma * HID_ + n) = p0;
            *reinterpret_cast<uint32_t*>(g_h1 + (size_t)mb * HID_ + n) = p1;
        }
    }
}

// ======================= GEMM2: TBM=64 x BN=128 =============================
// out = [x_f16, h1_f16] @ (W2h+W2l)^T + b2
__global__ __launch_bounds__(256, 1)
void gemm2_hmma(const __grid_constant__ CUtensorMap a0,
                const __grid_constant__ CUtensorMap a1,
                const __grid_constant__ CUtensorMap bh,
                const __grid_constant__ CUtensorMap bl,
                const float* __restrict__ bias,
                float* __restrict__ outp)
{
    constexpr int NST = 3;
    constexpr int TBM = 64;
    constexpr int MI = 2;
    constexpr uint32_t ASZ = 8192;
    constexpr uint32_t STG_A  = 0;
    constexpr uint32_t STG_BH = ASZ;
    constexpr uint32_t STG_BL = ASZ + 16384u;
    constexpr uint32_t STAGE_SZ = ASZ + 32768u;   // 40960

    extern __shared__ __align__(1024) char smem[];
    const uint32_t sbase = smem_u32(smem);

    const int tid  = threadIdx.x;
    const int lane = tid & 31;
    const int wid  = tid >> 5;
    const int wm   = (wid & 1) * 32;
    const int wn   = (wid >> 1) * 32;

    if (tid == 0) {
        #pragma unroll
        for (int s = 0; s < NST; s++) {
            MBARRIER_INIT(sbase + 8u * s, 1);
            MBARRIER_INIT(sbase + 64u + 8u * s, 8);
        }
        FENCE_PROXY_ASYNC();
    }
    __syncthreads();

    const int m0 = blockIdx.x * TBM;
    const int n0 = blockIdx.y * 128;
    const int S0 = DIN_ / KC;
    const int T  = K2_ / KC;

    const uint32_t rowoff = (uint32_t)(lane & 15) * 128u;
    const uint32_t hi4 = (uint32_t)(lane >> 4);
    const uint32_t lo7 = (uint32_t)(lane & 7);
    uint32_t cb[4];
    #pragma unroll
    for (int ks = 0; ks < 4; ks++)
        cb[ks] = (((2u * ks + hi4) ^ lo7) << 4);

    float acc[MI][4][4];
    #pragma unroll
    for (int mi = 0; mi < MI; mi++)
        #pragma unroll
        for (int ni = 0; ni < 4; ni++)
            #pragma unroll
            for (int q = 0; q < 4; q++) acc[mi][ni][q] = 0.f;

    if (tid == 0) {
        #pragma unroll
        for (int j = 0; j < NST; j++) {
            const uint32_t full = sbase + 8u * j;
            MBARRIER_EXPECT_TX(full, STAGE_SZ);
            const uint32_t sb = sbase + STAGE0_OFF + (uint32_t)j * STAGE_SZ;
            const CUtensorMap* ma_; int ak, bk;
            if (j < S0) { ma_ = &a0; ak = j * KC; bk = j * KC; }
            else        { ma_ = &a1; ak = (j - S0) * KC; bk = DIN_ + (j - S0) * KC; }
            tma2d(sb + STG_A,  ma_, ak, m0, full);
            tma2d(sb + STG_BH, &bh, bk, n0, full);
            tma2d(sb + STG_BL, &bl, bk, n0, full);
        }
    }

    int s = 0, ph = 0;
    #pragma unroll 1
    for (int i = 0; i < T; i++) {
        MBARRIER_WAIT_PARITY(sbase + 8u * s, (uint32_t)ph);

        const uint32_t sb  = sbase + STAGE0_OFF + (uint32_t)s * STAGE_SZ;
        const uint32_t aB  = sb + STG_A  + (uint32_t)wm * 128u + rowoff;
        const uint32_t bHb = sb + STG_BH + (uint32_t)wn * 128u + rowoff;
        const uint32_t bLb = sb + STG_BL + (uint32_t)wn * 128u + rowoff;

        #pragma unroll
        for (int ks = 0; ks < 4; ks++) {
            uint32_t aa[MI][4], bb[2][4];
            #pragma unroll
            for (int mi = 0; mi < MI; mi++)
                ldsm4(aa[mi], aB + (uint32_t)mi * (16u * 128u) + cb[ks]);
            #pragma unroll
            for (int nj = 0; nj < 2; nj++)
                ldsm4(bb[nj], bHb + (uint32_t)nj * (16u * 128u) + cb[ks]);

            #pragma unroll
            for (int mi = 0; mi < MI; mi++)
                #pragma unroll
                for (int ni = 0; ni < 4; ni++) {
                    const uint32_t b0 = bb[ni >> 1][ni & 1];
                    const uint32_t b1 = bb[ni >> 1][(ni & 1) + 2];
                    mma16816(acc[mi][ni], aa[mi], b0, b1);
                }
            #pragma unroll
            for (int nj = 0; nj < 2; nj++)
                ldsm4(bb[nj], bLb + (uint32_t)nj * (16u * 128u) + cb[ks]);
            #pragma unroll
            for (int mi = 0; mi < MI; mi++)
                #pragma unroll
                for (int ni = 0; ni < 4; ni++) {
                    const uint32_t b0 = bb[ni >> 1][ni & 1];
                    const uint32_t b1 = bb[ni >> 1][(ni & 1) + 2];
                    mma16816(acc[mi][ni], aa[mi], b0, b1);
                }
        }

        if (lane == 0) MBARRIER_ARRIVE(sbase + 64u + 8u * s);

        const int j = i + NST;
        if (tid == 0 && j < T) {
            MBARRIER_WAIT_PARITY(sbase + 64u + 8u * s, (uint32_t)ph);
            const uint32_t full = sbase + 8u * s;
            MBARRIER_EXPECT_TX(full, STAGE_SZ);
            const CUtensorMap* ma_; int ak, bk;
            if (j < S0) { ma_ = &a0; ak = j * KC; bk = j * KC; }
            else        { ma_ = &a1; ak = (j - S0) * KC; bk = DIN_ + (j - S0) * KC; }
            tma2d(sb + STG_A,  ma_, ak, m0, full);
            tma2d(sb + STG_BH, &bh, bk, n0, full);
            tma2d(sb + STG_BL, &bl, bk, n0, full);
        }
        if (++s == NST) { s = 0; ph ^= 1; }
    }

    const int mrow = m0 + wm + (lane >> 2);
    const int ncol = n0 + wn + 2 * (lane & 3);

    #pragma unroll
    for (int mi = 0; mi < MI; mi++) {
        #pragma unroll
        for (int ni = 0; ni < 4; ni++) {
            const int n = ncol + ni * 8;
            const int ma = mrow + mi * 16;
            const int mb = ma + 8;
            if (n >= ONN_) continue;
            const float2 bv = __ldg(reinterpret_cast<const float2*>(bias + n));
            float2 o0 = { acc[mi][ni][0] + bv.x, acc[mi][ni][1] + bv.y };
            float2 o1 = { acc[mi][ni][2] + bv.x, acc[mi][ni][3] + bv.y };
            *reinterpret_cast<float2*>(outp + (size_t)ma * ONN_ + n) = o0;
            *reinterpret_cast<float2*>(outp + (size_t)mb * ONN_ + n) = o1;
        }
    }
}

// ---------------- host side ---------------------
typedef CUresult (*PFN_tmap)(CUtensorMap*, CUtensorMapDataType, cuuint32_t, void*,
                             const cuuint64_t*, const cuuint64_t*, const cuuint32_t*,
                             const cuuint32_t*, CUtensorMapInterleave, CUtensorMapSwizzle,
                             CUtensorMapL2promotion, CUtensorMapFloatOOBfill);

static void mk2d(PFN_tmap f, CUtensorMap* m, void* p,
                 unsigned long long k, unsigned long long rows, unsigned box1)
{
    cuuint64_t dims[2] = { k, rows };
    cuuint64_t str[1]  = { k * 2 };
    cuuint32_t box[2]  = { 64u, box1 };
    cuuint32_t es[2]   = { 1u, 1u };
    f(m, CU_TENSOR_MAP_DATA_TYPE_FLOAT16, 2, p, dims, str, box, es,
      CU_TENSOR_MAP_INTERLEAVE_NONE, CU_TENSOR_MAP_SWIZZLE_128B,
      CU_TENSOR_MAP_L2_PROMOTION_L2_128B, CU_TENSOR_MAP_FLOAT_OOB_FILL_NONE);
}

extern "C" void kernel_launch(void* const* d_in, const int* in_sizes, int n_in,
                              void* d_out, int out_size)
{
    const float* x  = (const float*)d_in[0];
    const float* W1 = (const float*)d_in[1];
    const float* b1 = (const float*)d_in[2];
    const float* W2 = (const float*)d_in[3];
    const float* b2 = (const float*)d_in[4];
    float* out = (float*)d_out;

    void *xf, *w1h, *w1l, *w2h, *w2l, *h1;
    cudaGetSymbolAddress(&xf,  g_xf);
    cudaGetSymbolAddress(&w1h, g_w1h); cudaGetSymbolAddress(&w1l, g_w1l);
    cudaGetSymbolAddress(&w2h, g_w2h); cudaGetSymbolAddress(&w2l, g_w2l);
    cudaGetSymbolAddress(&h1,  g_h1);

    {
        size_t n4x  = (size_t)MB_ * DIN_ / 4;
        size_t n4w1 = (size_t)HID_ * DIN_ / 4;
        size_t n4w2 = (size_t)ONN_ * K2_ / 4;
        conv_f16 <<<(unsigned)((n4x  + 255) / 256), 256>>>(x,  (__half*)xf, n4x);
        split_f16<<<(unsigned)((n4w1 + 255) / 256), 256>>>(W1, (__half*)w1h, (__half*)w1l, n4w1);
        split_f16<<<(unsigned)((n4w2 + 255) / 256), 256>>>(W2, (__half*)w2h, (__half*)w2l, n4w2);
    }

    PFN_tmap enc = nullptr;
    cudaDriverEntryPointQueryResult qr;
    cudaGetDriverEntryPoint("cuTensorMapEncodeTiled", (void**)&enc,
                            cudaEnableDefault, &qr);

    CUtensorMap m_x128, m_x64, m_h164, m_w1h, m_w1l, m_w2h, m_w2l;
    mk2d(enc, &m_x128, xf, DIN_, MB_,  128);
    mk2d(enc, &m_x64,  xf, DIN_, MB_,  64);
    mk2d(enc, &m_h164, h1, HID_, MB_,  64);
    mk2d(enc, &m_w1h,  w1h, DIN_, HID_, 256);
    mk2d(enc, &m_w1l,  w1l, DIN_, HID_, 256);
    mk2d(enc, &m_w2h,  w2h, K2_,  ONN_, 128);
    mk2d(enc, &m_w2l,  w2l, K2_,  ONN_, 128);

    const int smem1 = STAGE0_OFF + 2 * 81920;   // 164864
    const int smem2 = STAGE0_OFF + 3 * 40960;   // 123904
    cudaFuncSetAttribute(gemm1_hmma, cudaFuncAttributeMaxDynamicSharedMemorySize, smem1);
    cudaFuncSetAttribute(gemm2_hmma, cudaFuncAttributeMaxDynamicSharedMemorySize, smem2);

    // GEMM1: h1 = relu(x @ W1^T + b1)
    dim3 g1(MB_ / 128, HID_ / 256);   // (32, 64)
    gemm1_hmma<<<g1, 256, smem1>>>(m_x128, m_w1h, m_w1l, b1);

    // GEMM2: out = [x, h1] @ W2^T + b2
    dim3 g2(MB_ / 64, 8);             // (64, 8)
    gemm2_hmma<<<g2, 256, smem2>>>(m_x64, m_h164, m_w2h, m_w2l, b2, out);
}

// round 9
// speedup vs baseline: 4.6808x; 1.0871x over previous
#include <cuda_runtime.h>
#include <cuda_fp16.h>
#include <cuda.h>
#include <cstdint>
#include <cstddef>

// ---------------- problem dims ----------------
#define MB_   4096
#define DIN_  4096
#define HID_  16384
#define ONN_  1000
#define K2_   (DIN_ + HID_)

#define KC 64                   // fp16 K per stage (128 B rows = SW128 atom)
#define STAGE0_OFF 1024
#define KSPLIT 4
#define KSEG   (K2_ / KSPLIT)   // 5120

// fp16 scratch (static device arrays — no allocation)
__device__ __align__(1024) __half g_xf [(size_t)MB_ * DIN_];
__device__ __align__(1024) __half g_w1h[(size_t)HID_ * DIN_];
__device__ __align__(1024) __half g_w1l[(size_t)HID_ * DIN_];
__device__ __align__(1024) __half g_w2h[(size_t)ONN_ * K2_];
__device__ __align__(1024) __half g_w2l[(size_t)ONN_ * K2_];
__device__ __align__(1024) __half g_h1 [(size_t)MB_ * HID_];
__device__ __align__(1024) float  g_p2 [(size_t)KSPLIT * MB_ * 1024];

// ---------------- PTX helpers ------------------
__device__ __forceinline__ uint32_t smem_u32(const void* p) {
    uint32_t a;
    asm("{ .reg .u64 t; cvta.to.shared.u64 t, %1; cvt.u32.u64 %0, t; }"
        : "=r"(a) : "l"(p));
    return a;
}

#define MBARRIER_INIT(addr, cnt) \
    asm volatile("mbarrier.init.shared.b64 [%0], %1;" :: "r"(addr), "r"(cnt) : "memory")

#define MBARRIER_EXPECT_TX(addr, bytes) \
    asm volatile("mbarrier.arrive.expect_tx.shared.b64 _, [%0], %1;" \
                 :: "r"(addr), "r"(bytes) : "memory")

#define MBARRIER_ARRIVE(addr) \
    asm volatile("mbarrier.arrive.shared.b64 _, [%0];" :: "r"(addr) : "memory")

#define MBARRIER_WAIT_PARITY(addr, parity) do {                                   \
    uint32_t _m = (addr); uint32_t _p = (parity); uint32_t _d;                    \
    asm volatile("{ .reg .pred p; mbarrier.try_wait.parity.acquire.cta.shared::cta.b64 p, [%1], %2; selp.b32 %0, 1, 0, p; }" \
        : "=r"(_d) : "r"(_m), "r"(_p) : "memory");                                \
    if (!_d) {                                                                    \
        asm volatile("{ .reg .pred P1; WL_%=: mbarrier.try_wait.parity.acquire.cta.shared::cta.b64 P1, [%0], %1, 0x989680; @P1 bra.uni WD_%=; bra.uni WL_%=; WD_%=: }" \
            :: "r"(_m), "r"(_p) : "memory");                                      \
    }                                                                             \
} while (0)

__device__ __forceinline__ void tma2d(uint32_t dst, const CUtensorMap* m,
                                      int cx, int cy, uint32_t mbar) {
    asm volatile(
        "cp.async.bulk.tensor.2d.shared::cta.global.tile.mbarrier::complete_tx::bytes "
        "[%0], [%1, {%2, %3}], [%4];"
        :: "r"(dst), "l"(m), "r"(cx), "r"(cy), "r"(mbar) : "memory");
}

#define FENCE_PROXY_ASYNC() asm volatile("fence.proxy.async.shared::cta;" ::: "memory")

__device__ __forceinline__ void ldsm4(uint32_t* r, uint32_t addr) {
    asm volatile("ldmatrix.sync.aligned.m8n8.x4.shared.b16 {%0,%1,%2,%3}, [%4];"
                 : "=r"(r[0]), "=r"(r[1]), "=r"(r[2]), "=r"(r[3]) : "r"(addr));
}

__device__ __forceinline__ void mma16816(float* c, const uint32_t* a, uint32_t b0, uint32_t b1) {
    asm volatile(
        "mma.sync.aligned.m16n8k16.row.col.f32.f16.f16.f32 "
        "{%0,%1,%2,%3}, {%4,%5,%6,%7}, {%8,%9}, {%0,%1,%2,%3};"
        : "+f"(c[0]), "+f"(c[1]), "+f"(c[2]), "+f"(c[3])
        : "r"(a[0]), "r"(a[1]), "r"(a[2]), "r"(a[3]), "r"(b0), "r"(b1));
}

// ---------------- conversions --------------
__global__ void conv_f16(const float* __restrict__ src,
                         __half* __restrict__ dst, size_t n4)
{
    size_t i = (size_t)blockIdx.x * blockDim.x + threadIdx.x;
    if (i >= n4) return;
    float4 v = reinterpret_cast<const float4*>(src)[i];
    __half h0 = __float2half_rn(v.x);
    __half h1 = __float2half_rn(v.y);
    __half h2 = __float2half_rn(v.z);
    __half h3 = __float2half_rn(v.w);
    uint2 p;
    p.x = (uint32_t)__half_as_ushort(h0) | ((uint32_t)__half_as_ushort(h1) << 16);
    p.y = (uint32_t)__half_as_ushort(h2) | ((uint32_t)__half_as_ushort(h3) << 16);
    reinterpret_cast<uint2*>(dst)[i] = p;
}

__global__ void split_f16(const float* __restrict__ src,
                          __half* __restrict__ hi,
                          __half* __restrict__ lo, size_t n4)
{
    size_t i = (size_t)blockIdx.x * blockDim.x + threadIdx.x;
    if (i >= n4) return;
    float4 v = reinterpret_cast<const float4*>(src)[i];
    __half h0 = __float2half_rn(v.x);
    __half h1 = __float2half_rn(v.y);
    __half h2 = __float2half_rn(v.z);
    __half h3 = __float2half_rn(v.w);
    __half l0 = __float2half_rn(v.x - __half2float(h0));
    __half l1 = __float2half_rn(v.y - __half2float(h1));
    __half l2 = __float2half_rn(v.z - __half2float(h2));
    __half l3 = __float2half_rn(v.w - __half2float(h3));
    uint2 ph, pl;
    ph.x = (uint32_t)__half_as_ushort(h0) | ((uint32_t)__half_as_ushort(h1) << 16);
    ph.y = (uint32_t)__half_as_ushort(h2) | ((uint32_t)__half_as_ushort(h3) << 16);
    pl.x = (uint32_t)__half_as_ushort(l0) | ((uint32_t)__half_as_ushort(l1) << 16);
    pl.y = (uint32_t)__half_as_ushort(l2) | ((uint32_t)__half_as_ushort(l3) << 16);
    reinterpret_cast<uint2*>(hi)[i] = ph;
    reinterpret_cast<uint2*>(lo)[i] = pl;
}

// ======================= GEMM1: BM=128 x BN=256, warp tile 64x64 =============
// h1 = relu(x_f16 @ (W1h+W1l)^T + b1) -> fp16    [unchanged from R8]
__global__ __launch_bounds__(256, 1)
void gemm1_hmma(const __grid_constant__ CUtensorMap a_m,
                const __grid_constant__ CUtensorMap bh_m,
                const __grid_constant__ CUtensorMap bl_m,
                const float* __restrict__ bias)
{
    constexpr int NST = 2;
    constexpr uint32_t STG_A  = 0;
    constexpr uint32_t STG_BH = 16384;
    constexpr uint32_t STG_BL = 49152;
    constexpr uint32_t STAGE_SZ = 81920;

    extern __shared__ __align__(1024) char smem[];
    const uint32_t sbase = smem_u32(smem);

    const int tid  = threadIdx.x;
    const int lane = tid & 31;
    const int wid  = tid >> 5;
    const int wm   = (wid & 1) * 64;
    const int wn   = (wid >> 1) * 64;

    if (tid == 0) {
        #pragma unroll
        for (int s = 0; s < NST; s++) {
            MBARRIER_INIT(sbase + 8u * s, 1);
            MBARRIER_INIT(sbase + 64u + 8u * s, 8);
        }
        FENCE_PROXY_ASYNC();
    }
    __syncthreads();

    const int m0 = blockIdx.x * 128;
    const int n0 = blockIdx.y * 256;
    const int T  = DIN_ / KC;

    const uint32_t rowoff = (uint32_t)(lane & 15) * 128u;
    const uint32_t hi4 = (uint32_t)(lane >> 4);
    const uint32_t lo7 = (uint32_t)(lane & 7);
    uint32_t cb[4];
    #pragma unroll
    for (int ks = 0; ks < 4; ks++)
        cb[ks] = (((2u * ks + hi4) ^ lo7) << 4);

    float acc[4][8][4];
    #pragma unroll
    for (int mi = 0; mi < 4; mi++)
        #pragma unroll
        for (int ni = 0; ni < 8; ni++)
            #pragma unroll
            for (int q = 0; q < 4; q++) acc[mi][ni][q] = 0.f;

    if (tid == 0) {
        #pragma unroll
        for (int j = 0; j < NST; j++) {
            const uint32_t full = sbase + 8u * j;
            MBARRIER_EXPECT_TX(full, STAGE_SZ);
            const uint32_t sb = sbase + STAGE0_OFF + (uint32_t)j * STAGE_SZ;
            tma2d(sb + STG_A,  &a_m,  j * KC, m0, full);
            tma2d(sb + STG_BH, &bh_m, j * KC, n0, full);
            tma2d(sb + STG_BL, &bl_m, j * KC, n0, full);
        }
    }

    int s = 0, ph = 0;
    #pragma unroll 1
    for (int i = 0; i < T; i++) {
        MBARRIER_WAIT_PARITY(sbase + 8u * s, (uint32_t)ph);

        const uint32_t sb  = sbase + STAGE0_OFF + (uint32_t)s * STAGE_SZ;
        const uint32_t aB  = sb + STG_A  + (uint32_t)wm * 128u + rowoff;
        const uint32_t bHb = sb + STG_BH + (uint32_t)wn * 128u + rowoff;
        const uint32_t bLb = sb + STG_BL + (uint32_t)wn * 128u + rowoff;

        #pragma unroll
        for (int ks = 0; ks < 4; ks++) {
            uint32_t aa[4][4], bb[4][4];
            #pragma unroll
            for (int mi = 0; mi < 4; mi++)
                ldsm4(aa[mi], aB + (uint32_t)mi * (16u * 128u) + cb[ks]);
            #pragma unroll
            for (int nj = 0; nj < 4; nj++)
                ldsm4(bb[nj], bHb + (uint32_t)nj * (16u * 128u) + cb[ks]);

            #pragma unroll
            for (int mi = 0; mi < 4; mi++)
                #pragma unroll
                for (int ni = 0; ni < 8; ni++) {
                    const uint32_t b0 = bb[ni >> 1][ni & 1];
                    const uint32_t b1 = bb[ni >> 1][(ni & 1) + 2];
                    mma16816(acc[mi][ni], aa[mi], b0, b1);
                }
            #pragma unroll
            for (int nj = 0; nj < 4; nj++)
                ldsm4(bb[nj], bLb + (uint32_t)nj * (16u * 128u) + cb[ks]);
            #pragma unroll
            for (int mi = 0; mi < 4; mi++)
                #pragma unroll
                for (int ni = 0; ni < 8; ni++) {
                    const uint32_t b0 = bb[ni >> 1][ni & 1];
                    const uint32_t b1 = bb[ni >> 1][(ni & 1) + 2];
                    mma16816(acc[mi][ni], aa[mi], b0, b1);
                }
        }

        if (lane == 0) MBARRIER_ARRIVE(sbase + 64u + 8u * s);

        const int j = i + NST;
        if (tid == 0 && j < T) {
            MBARRIER_WAIT_PARITY(sbase + 64u + 8u * s, (uint32_t)ph);
            const uint32_t full = sbase + 8u * s;
            MBARRIER_EXPECT_TX(full, STAGE_SZ);
            tma2d(sb + STG_A,  &a_m,  j * KC, m0, full);
            tma2d(sb + STG_BH, &bh_m, j * KC, n0, full);
            tma2d(sb + STG_BL, &bl_m, j * KC, n0, full);
        }
        if (++s == NST) { s = 0; ph ^= 1; }
    }

    const int mrow = m0 + wm + (lane >> 2);
    const int ncol = n0 + wn + 2 * (lane & 3);

    #pragma unroll
    for (int mi = 0; mi < 4; mi++) {
        #pragma unroll
        for (int ni = 0; ni < 8; ni++) {
            const int n = ncol + ni * 8;
            const int ma = mrow + mi * 16;
            const int mb = ma + 8;
            const float2 bv = __ldg(reinterpret_cast<const float2*>(bias + n));
            float v00 = acc[mi][ni][0] + bv.x;
            float v01 = acc[mi][ni][1] + bv.y;
            float v10 = acc[mi][ni][2] + bv.x;
            float v11 = acc[mi][ni][3] + bv.y;
            v00 = v00 > 0.f ? v00 : 0.f;
            v01 = v01 > 0.f ? v01 : 0.f;
            v10 = v10 > 0.f ? v10 : 0.f;
            v11 = v11 > 0.f ? v11 : 0.f;
            uint32_t p0 = (uint32_t)__half_as_ushort(__float2half_rn(v00))
                        | ((uint32_t)__half_as_ushort(__float2half_rn(v01)) << 16);
            uint32_t p1 = (uint32_t)__half_as_ushort(__float2half_rn(v10))
                        | ((uint32_t)__half_as_ushort(__float2half_rn(v11)) << 16);
            *reinterpret_cast<uint32_t*>(g_h1 + (size_t)ma * HID_ + n) = p0;
            *reinterpret_cast<uint32_t*>(g_h1 + (size_t)mb * HID_ + n) = p1;
        }
    }
}

// ========== GEMM2: split-K, TBM=128 x BN=128, 4 warps, warp tile 64x64 =======
// partial[z] = A[:, z*KSEG:(z+1)*KSEG] @ B[:, same]^T   (2-pass fp16 W split)
__global__ __launch_bounds__(128, 2)
void gemm2_hmma(const __grid_constant__ CUtensorMap a0,
                const __grid_constant__ CUtensorMap a1,
                const __grid_constant__ CUtensorMap bh,
                const __grid_constant__ CUtensorMap bl)
{
    constexpr int NST = 2;
    constexpr uint32_t STG_A  = 0;
    constexpr uint32_t STG_BH = 16384;
    constexpr uint32_t STG_BL = 32768;
    constexpr uint32_t STAGE_SZ = 49152;
    constexpr int T = KSEG / KC;    // 80

    extern __shared__ __align__(1024) char smem[];
    const uint32_t sbase = smem_u32(smem);

    const int tid  = threadIdx.x;
    const int lane = tid & 31;
    const int wid  = tid >> 5;
    const int wm   = (wid & 1) * 64;
    const int wn   = (wid >> 1) * 64;

    if (tid == 0) {
        #pragma unroll
        for (int s = 0; s < NST; s++) {
            MBARRIER_INIT(sbase + 8u * s, 1);
            MBARRIER_INIT(sbase + 64u + 8u * s, 4);
        }
        FENCE_PROXY_ASYNC();
    }
    __syncthreads();

    const int m0 = blockIdx.x * 128;
    const int n0 = blockIdx.y * 128;
    const int kb = blockIdx.z * KSEG;

    const uint32_t rowoff = (uint32_t)(lane & 15) * 128u;
    const uint32_t hi4 = (uint32_t)(lane >> 4);
    const uint32_t lo7 = (uint32_t)(lane & 7);
    uint32_t cb[4];
    #pragma unroll
    for (int ks = 0; ks < 4; ks++)
        cb[ks] = (((2u * ks + hi4) ^ lo7) << 4);

    float acc[4][8][4];
    #pragma unroll
    for (int mi = 0; mi < 4; mi++)
        #pragma unroll
        for (int ni = 0; ni < 8; ni++)
            #pragma unroll
            for (int q = 0; q < 4; q++) acc[mi][ni][q] = 0.f;

    if (tid == 0) {
        #pragma unroll
        for (int j = 0; j < NST; j++) {
            const uint32_t full = sbase + 8u * j;
            MBARRIER_EXPECT_TX(full, STAGE_SZ);
            const uint32_t sb = sbase + STAGE0_OFF + (uint32_t)j * STAGE_SZ;
            const int gk = kb + j * KC;
            if (gk < DIN_) tma2d(sb + STG_A, &a0, gk, m0, full);
            else           tma2d(sb + STG_A, &a1, gk - DIN_, m0, full);
            tma2d(sb + STG_BH, &bh, gk, n0, full);
            tma2d(sb + STG_BL, &bl, gk, n0, full);
        }
    }

    int s = 0, ph = 0;
    #pragma unroll 1
    for (int i = 0; i < T; i++) {
        MBARRIER_WAIT_PARITY(sbase + 8u * s, (uint32_t)ph);

        const uint32_t sb  = sbase + STAGE0_OFF + (uint32_t)s * STAGE_SZ;
        const uint32_t aB  = sb + STG_A  + (uint32_t)wm * 128u + rowoff;
        const uint32_t bHb = sb + STG_BH + (uint32_t)wn * 128u + rowoff;
        const uint32_t bLb = sb + STG_BL + (uint32_t)wn * 128u + rowoff;

        #pragma unroll
        for (int ks = 0; ks < 4; ks++) {
            uint32_t aa[4][4], bb[4][4];
            #pragma unroll
            for (int mi = 0; mi < 4; mi++)
                ldsm4(aa[mi], aB + (uint32_t)mi * (16u * 128u) + cb[ks]);
            #pragma unroll
            for (int nj = 0; nj < 4; nj++)
                ldsm4(bb[nj], bHb + (uint32_t)nj * (16u * 128u) + cb[ks]);

            #pragma unroll
            for (int mi = 0; mi < 4; mi++)
                #pragma unroll
                for (int ni = 0; ni < 8; ni++) {
                    const uint32_t b0 = bb[ni >> 1][ni & 1];
                    const uint32_t b1 = bb[ni >> 1][(ni & 1) + 2];
                    mma16816(acc[mi][ni], aa[mi], b0, b1);
                }
            #pragma unroll
            for (int nj = 0; nj < 4; nj++)
                ldsm4(bb[nj], bLb + (uint32_t)nj * (16u * 128u) + cb[ks]);
            #pragma unroll
            for (int mi = 0; mi < 4; mi++)
                #pragma unroll
                for (int ni = 0; ni < 8; ni++) {
                    const uint32_t b0 = bb[ni >> 1][ni & 1];
                    const uint32_t b1 = bb[ni >> 1][(ni & 1) + 2];
                    mma16816(acc[mi][ni], aa[mi], b0, b1);
                }
        }

        if (lane == 0) MBARRIER_ARRIVE(sbase + 64u + 8u * s);

        const int j = i + NST;
        if (tid == 0 && j < T) {
            MBARRIER_WAIT_PARITY(sbase + 64u + 8u * s, (uint32_t)ph);
            const uint32_t full = sbase + 8u * s;
            MBARRIER_EXPECT_TX(full, STAGE_SZ);
            const int gk = kb + j * KC;
            if (gk < DIN_) tma2d(sb + STG_A, &a0, gk, m0, full);
            else           tma2d(sb + STG_A, &a1, gk - DIN_, m0, full);
            tma2d(sb + STG_BH, &bh, gk, n0, full);
            tma2d(sb + STG_BL, &bl, gk, n0, full);
        }
        if (++s == NST) { s = 0; ph ^= 1; }
    }

    // write fp32 partial (n padded to 1024; each slot written exactly once)
    float* part = g_p2 + (size_t)blockIdx.z * MB_ * 1024;
    const int mrow = m0 + wm + (lane >> 2);
    const int ncol = n0 + wn + 2 * (lane & 3);

    #pragma unroll
    for (int mi = 0; mi < 4; mi++) {
        #pragma unroll
        for (int ni = 0; ni < 8; ni++) {
            const int n = ncol + ni * 8;
            const int ma = mrow + mi * 16;
            const int mb = ma + 8;
            float2 o0 = { acc[mi][ni][0], acc[mi][ni][1] };
            float2 o1 = { acc[mi][ni][2], acc[mi][ni][3] };
            *reinterpret_cast<float2*>(part + (size_t)ma * 1024 + n) = o0;
            *reinterpret_cast<float2*>(part + (size_t)mb * 1024 + n) = o1;
        }
    }
}

// reduce partials + bias -> out
__global__ __launch_bounds__(256)
void reduce_k(const float* __restrict__ bias, float* __restrict__ outp)
{
    const size_t i = (size_t)blockIdx.x * blockDim.x + threadIdx.x;   // over 4096*500
    if (i >= (size_t)MB_ * (ONN_ / 2)) return;
    const int m = (int)(i / (ONN_ / 2));
    const int n = 2 * (int)(i % (ONN_ / 2));
    const size_t off = (size_t)m * 1024 + n;
    float2 s = *reinterpret_cast<const float2*>(g_p2 + off);
    #pragma unroll
    for (int z = 1; z < KSPLIT; z++) {
        float2 v = *reinterpret_cast<const float2*>(g_p2 + (size_t)z * MB_ * 1024 + off);
        s.x += v.x; s.y += v.y;
    }
    const float2 bv = __ldg(reinterpret_cast<const float2*>(bias + n));
    s.x += bv.x; s.y += bv.y;
    *reinterpret_cast<float2*>(outp + (size_t)m * ONN_ + n) = s;
}

// ---------------- host side ---------------------
typedef CUresult (*PFN_tmap)(CUtensorMap*, CUtensorMapDataType, cuuint32_t, void*,
                             const cuuint64_t*, const cuuint64_t*, const cuuint32_t*,
                             const cuuint32_t*, CUtensorMapInterleave, CUtensorMapSwizzle,
                             CUtensorMapL2promotion, CUtensorMapFloatOOBfill);

static void mk2d(PFN_tmap f, CUtensorMap* m, void* p,
                 unsigned long long k, unsigned long long rows, unsigned box1)
{
    cuuint64_t dims[2] = { k, rows };
    cuuint64_t str[1]  = { k * 2 };
    cuuint32_t box[2]  = { 64u, box1 };
    cuuint32_t es[2]   = { 1u, 1u };
    f(m, CU_TENSOR_MAP_DATA_TYPE_FLOAT16, 2, p, dims, str, box, es,
      CU_TENSOR_MAP_INTERLEAVE_NONE, CU_TENSOR_MAP_SWIZZLE_128B,
      CU_TENSOR_MAP_L2_PROMOTION_L2_128B, CU_TENSOR_MAP_FLOAT_OOB_FILL_NONE);
}

extern "C" void kernel_launch(void* const* d_in, const int* in_sizes, int n_in,
                              void* d_out, int out_size)
{
    const float* x  = (const float*)d_in[0];
    const float* W1 = (const float*)d_in[1];
    const float* b1 = (const float*)d_in[2];
    const float* W2 = (const float*)d_in[3];
    const float* b2 = (const float*)d_in[4];
    float* out = (float*)d_out;

    void *xf, *w1h, *w1l, *w2h, *w2l, *h1;
    cudaGetSymbolAddress(&xf,  g_xf);
    cudaGetSymbolAddress(&w1h, g_w1h); cudaGetSymbolAddress(&w1l, g_w1l);
    cudaGetSymbolAddress(&w2h, g_w2h); cudaGetSymbolAddress(&w2l, g_w2l);
    cudaGetSymbolAddress(&h1,  g_h1);

    {
        size_t n4x  = (size_t)MB_ * DIN_ / 4;
        size_t n4w1 = (size_t)HID_ * DIN_ / 4;
        size_t n4w2 = (size_t)ONN_ * K2_ / 4;
        conv_f16 <<<(unsigned)((n4x  + 255) / 256), 256>>>(x,  (__half*)xf, n4x);
        split_f16<<<(unsigned)((n4w1 + 255) / 256), 256>>>(W1, (__half*)w1h, (__half*)w1l, n4w1);
        split_f16<<<(unsigned)((n4w2 + 255) / 256), 256>>>(W2, (__half*)w2h, (__half*)w2l, n4w2);
    }

    PFN_tmap enc = nullptr;
    cudaDriverEntryPointQueryResult qr;
    cudaGetDriverEntryPoint("cuTensorMapEncodeTiled", (void**)&enc,
                            cudaEnableDefault, &qr);

    CUtensorMap m_x128, m_h1128, m_w1h, m_w1l, m_w2h, m_w2l;
    mk2d(enc, &m_x128,  xf, DIN_, MB_,  128);
    mk2d(enc, &m_h1128, h1, HID_, MB_,  128);
    mk2d(enc, &m_w1h,   w1h, DIN_, HID_, 256);
    mk2d(enc, &m_w1l,   w1l, DIN_, HID_, 256);
    mk2d(enc, &m_w2h,   w2h, K2_,  ONN_, 128);
    mk2d(enc, &m_w2l,   w2l, K2_,  ONN_, 128);

    const int smem1 = STAGE0_OFF + 2 * 81920;   // 164864
    const int smem2 = STAGE0_OFF + 2 * 49152;   // 99328 -> 2 CTAs/SM
    cudaFuncSetAttribute(gemm1_hmma, cudaFuncAttributeMaxDynamicSharedMemorySize, smem1);
    cudaFuncSetAttribute(gemm2_hmma, cudaFuncAttributeMaxDynamicSharedMemorySize, smem2);

    // GEMM1: h1 = relu(x @ W1^T + b1)
    dim3 g1(MB_ / 128, HID_ / 256);   // (32, 64)
    gemm1_hmma<<<g1, 256, smem1>>>(m_x128, m_w1h, m_w1l, b1);

    // GEMM2: split-K partials, then reduce
    dim3 g2(MB_ / 128, 8, KSPLIT);    // (32, 8, 4) = 1024 CTAs
    gemm2_hmma<<<g2, 128, smem2>>>(m_x128, m_h1128, m_w2h, m_w2l);

    const size_t nred = (size_t)MB_ * (ONN_ / 2);
    reduce_k<<<(unsigned)((nred + 255) / 256), 256>>>(b2, out);
}

// round 10
// speedup vs baseline: 8.2405x; 1.7605x over previous
#include <cuda_runtime.h>
#include <cuda_fp16.h>
#include <cuda.h>
#include <cstdint>
#include <cstddef>

// ---------------- problem dims ----------------
#define MB_   4096
#define DIN_  4096
#define HID_  16384
#define ONN_  1000
#define K2_   (DIN_ + HID_)

#define KC 64                   // fp16 K per stage (128 B rows = SW128 atom)
#define STAGE0_OFF 1024
#define KSPLIT 4
#define KSEG   (K2_ / KSPLIT)   // 5120

// fp16 scratch (static device arrays — no allocation)
__device__ __align__(1024) __half g_xf [(size_t)MB_ * DIN_];
__device__ __align__(1024) __half g_w1f[(size_t)HID_ * DIN_];
__device__ __align__(1024) __half g_w2f[(size_t)ONN_ * K2_];
__device__ __align__(1024) __half g_h1 [(size_t)MB_ * HID_];
__device__ __align__(1024) float  g_p2 [(size_t)KSPLIT * MB_ * 1024];

// ---------------- PTX helpers ------------------
__device__ __forceinline__ uint32_t smem_u32(const void* p) {
    uint32_t a;
    asm("{ .reg .u64 t; cvta.to.shared.u64 t, %1; cvt.u32.u64 %0, t; }"
        : "=r"(a) : "l"(p));
    return a;
}

#define MBARRIER_INIT(addr, cnt) \
    asm volatile("mbarrier.init.shared.b64 [%0], %1;" :: "r"(addr), "r"(cnt) : "memory")

#define MBARRIER_EXPECT_TX(addr, bytes) \
    asm volatile("mbarrier.arrive.expect_tx.shared.b64 _, [%0], %1;" \
                 :: "r"(addr), "r"(bytes) : "memory")

#define MBARRIER_ARRIVE(addr) \
    asm volatile("mbarrier.arrive.shared.b64 _, [%0];" :: "r"(addr) : "memory")

#define MBARRIER_WAIT_PARITY(addr, parity) do {                                   \
    uint32_t _m = (addr); uint32_t _p = (parity); uint32_t _d;                    \
    asm volatile("{ .reg .pred p; mbarrier.try_wait.parity.acquire.cta.shared::cta.b64 p, [%1], %2; selp.b32 %0, 1, 0, p; }" \
        : "=r"(_d) : "r"(_m), "r"(_p) : "memory");                                \
    if (!_d) {                                                                    \
        asm volatile("{ .reg .pred P1; WL_%=: mbarrier.try_wait.parity.acquire.cta.shared::cta.b64 P1, [%0], %1, 0x989680; @P1 bra.uni WD_%=; bra.uni WL_%=; WD_%=: }" \
            :: "r"(_m), "r"(_p) : "memory");                                      \
    }                                                                             \
} while (0)

__device__ __forceinline__ void tma2d(uint32_t dst, const CUtensorMap* m,
                                      int cx, int cy, uint32_t mbar) {
    asm volatile(
        "cp.async.bulk.tensor.2d.shared::cta.global.tile.mbarrier::complete_tx::bytes "
        "[%0], [%1, {%2, %3}], [%4];"
        :: "r"(dst), "l"(m), "r"(cx), "r"(cy), "r"(mbar) : "memory");
}

#define FENCE_PROXY_ASYNC() asm volatile("fence.proxy.async.shared::cta;" ::: "memory")

__device__ __forceinline__ void ldsm4(uint32_t* r, uint32_t addr) {
    asm volatile("ldmatrix.sync.aligned.m8n8.x4.shared.b16 {%0,%1,%2,%3}, [%4];"
                 : "=r"(r[0]), "=r"(r[1]), "=r"(r[2]), "=r"(r[3]) : "r"(addr));
}

__device__ __forceinline__ void mma16816(float* c, const uint32_t* a, uint32_t b0, uint32_t b1) {
    asm volatile(
        "mma.sync.aligned.m16n8k16.row.col.f32.f16.f16.f32 "
        "{%0,%1,%2,%3}, {%4,%5,%6,%7}, {%8,%9}, {%0,%1,%2,%3};"
        : "+f"(c[0]), "+f"(c[1]), "+f"(c[2]), "+f"(c[3])
        : "r"(a[0]), "r"(a[1]), "r"(a[2]), "r"(a[3]), "r"(b0), "r"(b1));
}

// ---------------- conversion --------------
__global__ void conv_f16(const float* __restrict__ src,
                         __half* __restrict__ dst, size_t n4)
{
    size_t i = (size_t)blockIdx.x * blockDim.x + threadIdx.x;
    if (i >= n4) return;
    float4 v = reinterpret_cast<const float4*>(src)[i];
    __half h0 = __float2half_rn(v.x);
    __half h1 = __float2half_rn(v.y);
    __half h2 = __float2half_rn(v.z);
    __half h3 = __float2half_rn(v.w);
    uint2 p;
    p.x = (uint32_t)__half_as_ushort(h0) | ((uint32_t)__half_as_ushort(h1) << 16);
    p.y = (uint32_t)__half_as_ushort(h2) | ((uint32_t)__half_as_ushort(h3) << 16);
    reinterpret_cast<uint2*>(dst)[i] = p;
}

// ======================= GEMM1: BM=128 x BN=256, warp tile 64x64 =============
// h1 = relu(x_f16 @ W1_f16^T + b1) -> fp16, single pass
__global__ __launch_bounds__(256, 1)
void gemm1_hmma(const __grid_constant__ CUtensorMap a_m,
                const __grid_constant__ CUtensorMap b_m,
                const float* __restrict__ bias)
{
    constexpr int NST = 2;
    constexpr uint32_t STG_A = 0;
    constexpr uint32_t STG_B = 16384;        // A is 128*128
    constexpr uint32_t STAGE_SZ = 49152;     // 16K A + 32K B

    extern __shared__ __align__(1024) char smem[];
    const uint32_t sbase = smem_u32(smem);

    const int tid  = threadIdx.x;
    const int lane = tid & 31;
    const int wid  = tid >> 5;
    const int wm   = (wid & 1) * 64;
    const int wn   = (wid >> 1) * 64;

    if (tid == 0) {
        #pragma unroll
        for (int s = 0; s < NST; s++) {
            MBARRIER_INIT(sbase + 8u * s, 1);
            MBARRIER_INIT(sbase + 64u + 8u * s, 8);
        }
        FENCE_PROXY_ASYNC();
    }
    __syncthreads();

    const int m0 = blockIdx.x * 128;
    const int n0 = blockIdx.y * 256;
    const int T  = DIN_ / KC;    // 64

    const uint32_t rowoff = (uint32_t)(lane & 15) * 128u;
    const uint32_t hi4 = (uint32_t)(lane >> 4);
    const uint32_t lo7 = (uint32_t)(lane & 7);
    uint32_t cb[4];
    #pragma unroll
    for (int ks = 0; ks < 4; ks++)
        cb[ks] = (((2u * ks + hi4) ^ lo7) << 4);

    float acc[4][8][4];
    #pragma unroll
    for (int mi = 0; mi < 4; mi++)
        #pragma unroll
        for (int ni = 0; ni < 8; ni++)
            #pragma unroll
            for (int q = 0; q < 4; q++) acc[mi][ni][q] = 0.f;

    if (tid == 0) {
        #pragma unroll
        for (int j = 0; j < NST; j++) {
            const uint32_t full = sbase + 8u * j;
            MBARRIER_EXPECT_TX(full, STAGE_SZ);
            const uint32_t sb = sbase + STAGE0_OFF + (uint32_t)j * STAGE_SZ;
            tma2d(sb + STG_A, &a_m, j * KC, m0, full);
            tma2d(sb + STG_B, &b_m, j * KC, n0, full);
        }
    }

    int s = 0, ph = 0;
    #pragma unroll 1
    for (int i = 0; i < T; i++) {
        MBARRIER_WAIT_PARITY(sbase + 8u * s, (uint32_t)ph);

        const uint32_t sb = sbase + STAGE0_OFF + (uint32_t)s * STAGE_SZ;
        const uint32_t aB = sb + STG_A + (uint32_t)wm * 128u + rowoff;
        const uint32_t bB = sb + STG_B + (uint32_t)wn * 128u + rowoff;

        #pragma unroll
        for (int ks = 0; ks < 4; ks++) {
            uint32_t aa[4][4], bb[4][4];
            #pragma unroll
            for (int mi = 0; mi < 4; mi++)
                ldsm4(aa[mi], aB + (uint32_t)mi * (16u * 128u) + cb[ks]);
            #pragma unroll
            for (int nj = 0; nj < 4; nj++)
                ldsm4(bb[nj], bB + (uint32_t)nj * (16u * 128u) + cb[ks]);

            #pragma unroll
            for (int mi = 0; mi < 4; mi++)
                #pragma unroll
                for (int ni = 0; ni < 8; ni++) {
                    const uint32_t b0 = bb[ni >> 1][ni & 1];
                    const uint32_t b1 = bb[ni >> 1][(ni & 1) + 2];
                    mma16816(acc[mi][ni], aa[mi], b0, b1);
                }
        }

        if (lane == 0) MBARRIER_ARRIVE(sbase + 64u + 8u * s);

        const int j = i + NST;
        if (tid == 0 && j < T) {
            MBARRIER_WAIT_PARITY(sbase + 64u + 8u * s, (uint32_t)ph);
            const uint32_t full = sbase + 8u * s;
            MBARRIER_EXPECT_TX(full, STAGE_SZ);
            tma2d(sb + STG_A, &a_m, j * KC, m0, full);
            tma2d(sb + STG_B, &b_m, j * KC, n0, full);
        }
        if (++s == NST) { s = 0; ph ^= 1; }
    }

    // epilogue: bias + relu -> fp16
    const int mrow = m0 + wm + (lane >> 2);
    const int ncol = n0 + wn + 2 * (lane & 3);

    #pragma unroll
    for (int mi = 0; mi < 4; mi++) {
        #pragma unroll
        for (int ni = 0; ni < 8; ni++) {
            const int n = ncol + ni * 8;
            const int ma = mrow + mi * 16;
            const int mb = ma + 8;
            const float2 bv = __ldg(reinterpret_cast<const float2*>(bias + n));
            float v00 = acc[mi][ni][0] + bv.x;
            float v01 = acc[mi][ni][1] + bv.y;
            float v10 = acc[mi][ni][2] + bv.x;
            float v11 = acc[mi][ni][3] + bv.y;
            v00 = v00 > 0.f ? v00 : 0.f;
            v01 = v01 > 0.f ? v01 : 0.f;
            v10 = v10 > 0.f ? v10 : 0.f;
            v11 = v11 > 0.f ? v11 : 0.f;
            uint32_t p0 = (uint32_t)__half_as_ushort(__float2half_rn(v00))
                        | ((uint32_t)__half_as_ushort(__float2half_rn(v01)) << 16);
            uint32_t p1 = (uint32_t)__half_as_ushort(__float2half_rn(v10))
                        | ((uint32_t)__half_as_ushort(__float2half_rn(v11)) << 16);
            *reinterpret_cast<uint32_t*>(g_h1 + (size_t)ma * HID_ + n) = p0;
            *reinterpret_cast<uint32_t*>(g_h1 + (size_t)mb * HID_ + n) = p1;
        }
    }
}

// ========== GEMM2: split-K, TBM=128 x BN=128, 4 warps, warp tile 64x64 =======
// partial[z] = A[:, z*KSEG:(z+1)*KSEG] @ W2_f16[:, same]^T, single pass
__global__ __launch_bounds__(128, 2)
void gemm2_hmma(const __grid_constant__ CUtensorMap a0,
                const __grid_constant__ CUtensorMap a1,
                const __grid_constant__ CUtensorMap b_m)
{
    constexpr int NST = 2;
    constexpr uint32_t STG_A = 0;
    constexpr uint32_t STG_B = 16384;
    constexpr uint32_t STAGE_SZ = 32768;
    constexpr int T = KSEG / KC;    // 80

    extern __shared__ __align__(1024) char smem[];
    const uint32_t sbase = smem_u32(smem);

    const int tid  = threadIdx.x;
    const int lane = tid & 31;
    const int wid  = tid >> 5;
    const int wm   = (wid & 1) * 64;
    const int wn   = (wid >> 1) * 64;

    if (tid == 0) {
        #pragma unroll
        for (int s = 0; s < NST; s++) {
            MBARRIER_INIT(sbase + 8u * s, 1);
            MBARRIER_INIT(sbase + 64u + 8u * s, 4);
        }
        FENCE_PROXY_ASYNC();
    }
    __syncthreads();

    const int m0 = blockIdx.x * 128;
    const int n0 = blockIdx.y * 128;
    const int kb = blockIdx.z * KSEG;

    const uint32_t rowoff = (uint32_t)(lane & 15) * 128u;
    const uint32_t hi4 = (uint32_t)(lane >> 4);
    const uint32_t lo7 = (uint32_t)(lane & 7);
    uint32_t cb[4];
    #pragma unroll
    for (int ks = 0; ks < 4; ks++)
        cb[ks] = (((2u * ks + hi4) ^ lo7) << 4);

    float acc[4][8][4];
    #pragma unroll
    for (int mi = 0; mi < 4; mi++)
        #pragma unroll
        for (int ni = 0; ni < 8; ni++)
            #pragma unroll
            for (int q = 0; q < 4; q++) acc[mi][ni][q] = 0.f;

    if (tid == 0) {
        #pragma unroll
        for (int j = 0; j < NST; j++) {
            const uint32_t full = sbase + 8u * j;
            MBARRIER_EXPECT_TX(full, STAGE_SZ);
            const uint32_t sb = sbase + STAGE0_OFF + (uint32_t)j * STAGE_SZ;
            const int gk = kb + j * KC;
            if (gk < DIN_) tma2d(sb + STG_A, &a0, gk, m0, full);
            else           tma2d(sb + STG_A, &a1, gk - DIN_, m0, full);
            tma2d(sb + STG_B, &b_m, gk, n0, full);
        }
    }

    int s = 0, ph = 0;
    #pragma unroll 1
    for (int i = 0; i < T; i++) {
        MBARRIER_WAIT_PARITY(sbase + 8u * s, (uint32_t)ph);

        const uint32_t sb = sbase + STAGE0_OFF + (uint32_t)s * STAGE_SZ;
        const uint32_t aB = sb + STG_A + (uint32_t)wm * 128u + rowoff;
        const uint32_t bB = sb + STG_B + (uint32_t)wn * 128u + rowoff;

        #pragma unroll
        for (int ks = 0; ks < 4; ks++) {
            uint32_t aa[4][4], bb[4][4];
            #pragma unroll
            for (int mi = 0; mi < 4; mi++)
                ldsm4(aa[mi], aB + (uint32_t)mi * (16u * 128u) + cb[ks]);
            #pragma unroll
            for (int nj = 0; nj < 4; nj++)
                ldsm4(bb[nj], bB + (uint32_t)nj * (16u * 128u) + cb[ks]);

            #pragma unroll
            for (int mi = 0; mi < 4; mi++)
                #pragma unroll
                for (int ni = 0; ni < 8; ni++) {
                    const uint32_t b0 = bb[ni >> 1][ni & 1];
                    const uint32_t b1 = bb[ni >> 1][(ni & 1) + 2];
                    mma16816(acc[mi][ni], aa[mi], b0, b1);
                }
        }

        if (lane == 0) MBARRIER_ARRIVE(sbase + 64u + 8u * s);

        const int j = i + NST;
        if (tid == 0 && j < T) {
            MBARRIER_WAIT_PARITY(sbase + 64u + 8u * s, (uint32_t)ph);
            const uint32_t full = sbase + 8u * s;
            MBARRIER_EXPECT_TX(full, STAGE_SZ);
            const int gk = kb + j * KC;
            if (gk < DIN_) tma2d(sb + STG_A, &a0, gk, m0, full);
            else           tma2d(sb + STG_A, &a1, gk - DIN_, m0, full);
            tma2d(sb + STG_B, &b_m, gk, n0, full);
        }
        if (++s == NST) { s = 0; ph ^= 1; }
    }

    // write fp32 partial (n padded to 1024; each slot written exactly once)
    float* part = g_p2 + (size_t)blockIdx.z * MB_ * 1024;
    const int mrow = m0 + wm + (lane >> 2);
    const int ncol = n0 + wn + 2 * (lane & 3);

    #pragma unroll
    for (int mi = 0; mi < 4; mi++) {
        #pragma unroll
        for (int ni = 0; ni < 8; ni++) {
            const int n = ncol + ni * 8;
            const int ma = mrow + mi * 16;
            const int mb = ma + 8;
            float2 o0 = { acc[mi][ni][0], acc[mi][ni][1] };
            float2 o1 = { acc[mi][ni][2], acc[mi][ni][3] };
            *reinterpret_cast<float2*>(part + (size_t)ma * 1024 + n) = o0;
            *reinterpret_cast<float2*>(part + (size_t)mb * 1024 + n) = o1;
        }
    }
}

// reduce partials + bias -> out
__global__ __launch_bounds__(256)
void reduce_k(const float* __restrict__ bias, float* __restrict__ outp)
{
    const size_t i = (size_t)blockIdx.x * blockDim.x + threadIdx.x;
    if (i >= (size_t)MB_ * (ONN_ / 2)) return;
    const int m = (int)(i / (ONN_ / 2));
    const int n = 2 * (int)(i % (ONN_ / 2));
    const size_t off = (size_t)m * 1024 + n;
    float2 s = *reinterpret_cast<const float2*>(g_p2 + off);
    #pragma unroll
    for (int z = 1; z < KSPLIT; z++) {
        float2 v = *reinterpret_cast<const float2*>(g_p2 + (size_t)z * MB_ * 1024 + off);
        s.x += v.x; s.y += v.y;
    }
    const float2 bv = __ldg(reinterpret_cast<const float2*>(bias + n));
    s.x += bv.x; s.y += bv.y;
    *reinterpret_cast<float2*>(outp + (size_t)m * ONN_ + n) = s;
}

// ---------------- host side ---------------------
typedef CUresult (*PFN_tmap)(CUtensorMap*, CUtensorMapDataType, cuuint32_t, void*,
                             const cuuint64_t*, const cuuint64_t*, const cuuint32_t*,
                             const cuuint32_t*, CUtensorMapInterleave, CUtensorMapSwizzle,
                             CUtensorMapL2promotion, CUtensorMapFloatOOBfill);

static void mk2d(PFN_tmap f, CUtensorMap* m, void* p,
                 unsigned long long k, unsigned long long rows, unsigned box1)
{
    cuuint64_t dims[2] = { k, rows };
    cuuint64_t str[1]  = { k * 2 };
    cuuint32_t box[2]  = { 64u, box1 };
    cuuint32_t es[2]   = { 1u, 1u };
    f(m, CU_TENSOR_MAP_DATA_TYPE_FLOAT16, 2, p, dims, str, box, es,
      CU_TENSOR_MAP_INTERLEAVE_NONE, CU_TENSOR_MAP_SWIZZLE_128B,
      CU_TENSOR_MAP_L2_PROMOTION_L2_128B, CU_TENSOR_MAP_FLOAT_OOB_FILL_NONE);
}

extern "C" void kernel_launch(void* const* d_in, const int* in_sizes, int n_in,
                              void* d_out, int out_size)
{
    const float* x  = (const float*)d_in[0];
    const float* W1 = (const float*)d_in[1];
    const float* b1 = (const float*)d_in[2];
    const float* W2 = (const float*)d_in[3];
    const float* b2 = (const float*)d_in[4];
    float* out = (float*)d_out;

    void *xf, *w1f, *w2f, *h1;
    cudaGetSymbolAddress(&xf,  g_xf);
    cudaGetSymbolAddress(&w1f, g_w1f);
    cudaGetSymbolAddress(&w2f, g_w2f);
    cudaGetSymbolAddress(&h1,  g_h1);

    {
        size_t n4x  = (size_t)MB_ * DIN_ / 4;
        size_t n4w1 = (size_t)HID_ * DIN_ / 4;
        size_t n4w2 = (size_t)ONN_ * K2_ / 4;
        conv_f16<<<(unsigned)((n4x  + 255) / 256), 256>>>(x,  (__half*)xf,  n4x);
        conv_f16<<<(unsigned)((n4w1 + 255) / 256), 256>>>(W1, (__half*)w1f, n4w1);
        conv_f16<<<(unsigned)((n4w2 + 255) / 256), 256>>>(W2, (__half*)w2f, n4w2);
    }

    PFN_tmap enc = nullptr;
    cudaDriverEntryPointQueryResult qr;
    cudaGetDriverEntryPoint("cuTensorMapEncodeTiled", (void**)&enc,
                            cudaEnableDefault, &qr);

    CUtensorMap m_x128, m_h1128, m_w1, m_w2;
    mk2d(enc, &m_x128,  xf, DIN_, MB_,  128);
    mk2d(enc, &m_h1128, h1, HID_, MB_,  128);
    mk2d(enc, &m_w1,    w1f, DIN_, HID_, 256);
    mk2d(enc, &m_w2,    w2f, K2_,  ONN_, 128);

    const int smem1 = STAGE0_OFF + 2 * 49152;   // 99328
    const int smem2 = STAGE0_OFF + 2 * 32768;   // 66560 -> 2 CTAs/SM
    cudaFuncSetAttribute(gemm1_hmma, cudaFuncAttributeMaxDynamicSharedMemorySize, smem1);
    cudaFuncSetAttribute(gemm2_hmma, cudaFuncAttributeMaxDynamicSharedMemorySize, smem2);

    // GEMM1: h1 = relu(x @ W1^T + b1)
    dim3 g1(MB_ / 128, HID_ / 256);   // (32, 64)
    gemm1_hmma<<<g1, 256, smem1>>>(m_x128, m_w1, b1);

    // GEMM2: split-K partials, then reduce
    dim3 g2(MB_ / 128, 8, KSPLIT);    // (32, 8, 4) = 1024 CTAs
    gemm2_hmma<<<g2, 128, smem2>>>(m_x128, m_h1128, m_w2);

    const size_t nred = (size_t)MB_ * (ONN_ / 2);
    reduce_k<<<(unsigned)((nred + 255) / 256), 256>>>(b2, out);
}